// round 9
// baseline (speedup 1.0000x reference)
#include <cuda_runtime.h>
#include <cuda_bf16.h>
#include <math.h>
#include <stdint.h>

// Problem constants (fixed by setup_inputs)
#define NN 50000
#define EE 800000
#define DD 128
#define LL 2
#define NCHUNK ((NN + 1023) / 1024)
#define CONVN (NN * DD / 4)

// ---------------- scratch (static __device__ globals; no allocation) ----------------
// g_cursor is zeroed by k_zero_end at the END of each launch (module-load zero-init
// covers the first call) — keeps the CSR build at 2 kernels.
__device__ float g_Z[NN * DD];
__device__ float g_HX[NN * DD];
__device__ float g_bias[LL * 384];
__device__ float g_invdeg[NN];
__device__ int g_rowptr[NN + 1];
__device__ int g_cursor[NN];
__device__ int g_esrc[EE];

__device__ __align__(16) __nv_bfloat16 g_inp_h[NN * DD], g_inp_l[NN * DD];
__device__ __align__(16) __nv_bfloat16 g_h_h[NN * DD],   g_h_l[NN * DD];
__device__ __align__(16) __nv_bfloat16 g_agga_h[NN * DD], g_agga_l[NN * DD];
__device__ __align__(16) __nv_bfloat16 g_aggb_h[NN * DD], g_aggb_l[NN * DD];
__device__ __align__(16) __nv_bfloat16 g_rh_h[NN * DD],  g_rh_l[NN * DD];
__device__ __align__(16) __nv_bfloat16 g_W1T_h[LL * 384 * 512], g_W1T_l[LL * 384 * 512];
__device__ __align__(16) __nv_bfloat16 g_W2T_h[LL * 128 * 256], g_W2T_l[LL * 128 * 256];

// ---------------- helpers ----------------
__device__ __forceinline__ uint32_t smem_u32(const void* p) {
    uint32_t a;
    asm("{ .reg .u64 t; cvta.to.shared.u64 t, %1; cvt.u32.u64 %0, t; }" : "=r"(a) : "l"(p));
    return a;
}
__device__ __forceinline__ void ldsm4(uint32_t* f, uint32_t addr) {
    asm volatile("ldmatrix.sync.aligned.m8n8.x4.shared.b16 {%0,%1,%2,%3}, [%4];"
                 : "=r"(f[0]), "=r"(f[1]), "=r"(f[2]), "=r"(f[3]) : "r"(addr));
}
__device__ __forceinline__ void mma16816(float* c, const uint32_t* a, uint32_t b0, uint32_t b1) {
    asm volatile(
        "mma.sync.aligned.m16n8k16.row.col.f32.bf16.bf16.f32 "
        "{%0,%1,%2,%3}, {%4,%5,%6,%7}, {%8,%9}, {%0,%1,%2,%3};"
        : "+f"(c[0]), "+f"(c[1]), "+f"(c[2]), "+f"(c[3])
        : "r"(a[0]), "r"(a[1]), "r"(a[2]), "r"(a[3]), "r"(b0), "r"(b1));
}
#define CPA_COMMIT() asm volatile("cp.async.commit_group;" ::: "memory")
#define CPA_WAIT0()  asm volatile("cp.async.wait_group 0;" ::: "memory")

__device__ __forceinline__ void split_bf16(float v, __nv_bfloat16& h, __nv_bfloat16& l) {
    h = __float2bfloat16(v);
    l = __float2bfloat16(v - __bfloat162float(h));
}
__device__ __forceinline__ void store_split4(__nv_bfloat16* dh, __nv_bfloat16* dl, float4 v) {
    union { __nv_bfloat16 b[4]; unsigned long long u; } H, L;
    split_bf16(v.x, H.b[0], L.b[0]);
    split_bf16(v.y, H.b[1], L.b[1]);
    split_bf16(v.z, H.b[2], L.b[2]);
    split_bf16(v.w, H.b[3], L.b[3]);
    *(unsigned long long*)dh = H.u;
    *(unsigned long long*)dl = L.u;
}
__device__ __forceinline__ void store_split2(__nv_bfloat16* dh, __nv_bfloat16* dl, float a, float b) {
    union { __nv_bfloat16 b2[2]; uint32_t u; } H, L;
    split_bf16(a, H.b2[0], L.b2[0]);
    split_bf16(b, H.b2[1], L.b2[1]);
    *(uint32_t*)dh = H.u;
    *(uint32_t*)dl = L.u;
}
__device__ __forceinline__ float sigf(float x) { return 1.0f / (1.0f + expf(-x)); }

// SMEM tile geometry: 128 rows x 32 bf16, padded row stride 80B (conflict-free ldmatrix)
#define TROW 80
#define TBYTES (128 * TROW)        // 10240
#define STAGE (4 * TBYTES)         // Ah,Al,Bh,Bl
#define GSMEM (2 * STAGE)          // 81920

// async load of a [128 x 32] bf16 tile into padded SMEM; OOB rows -> zero fill
__device__ __forceinline__ void tile_async(uint32_t dst, const __nv_bfloat16* __restrict__ src,
                                           int stride, int row_base, int col_base,
                                           int row_limit, int t) {
#pragma unroll
    for (int i = 0; i < 2; i++) {
        int idx = t + i * 256;
        int r = idx >> 2, q = idx & 3;
        int gr = row_base + r;
        bool ok = gr < row_limit;
        int grc = ok ? gr : 0;
        const void* s = src + (size_t)grc * stride + col_base + q * 8;
        int sz = ok ? 16 : 0;
        asm volatile("cp.async.cg.shared.global [%0], [%1], 16, %2;"
                     :: "r"(dst + (uint32_t)(r * TROW + q * 16)), "l"(s), "r"(sz) : "memory");
    }
}

// ---------------- CSR: fused count+scan (one kernel, no gmem degree array) ----------------
// Block b handles nodes [b*1024, b*1024+1024). It scans ALL edges once:
//  - counts edges with dst < lo (base offset), and
//  - histograms edges with dst in its window (smem atomics).
__global__ void __launch_bounds__(1024)
k_countscan(const int* __restrict__ dst) {
    __shared__ int hist[1024];
    __shared__ int ws[32];
    __shared__ int sbase;
    int b = blockIdx.x, t = threadIdx.x;
    int lane = t & 31, wid = t >> 5;
    hist[t] = 0;
    __syncthreads();

    int lo = b << 10;
    int pre = 0;
    const int4* d4 = (const int4*)dst;
    for (int e = t; e < EE / 4; e += 1024) {
        int4 v = __ldg(d4 + e);
        pre += (v.x < lo) + (v.y < lo) + (v.z < lo) + (v.w < lo);
        int dx;
        dx = v.x - lo; if ((unsigned)dx < 1024u) atomicAdd(&hist[dx], 1);
        dx = v.y - lo; if ((unsigned)dx < 1024u) atomicAdd(&hist[dx], 1);
        dx = v.z - lo; if ((unsigned)dx < 1024u) atomicAdd(&hist[dx], 1);
        dx = v.w - lo; if ((unsigned)dx < 1024u) atomicAdd(&hist[dx], 1);
    }
#pragma unroll
    for (int o = 16; o > 0; o >>= 1) pre += __shfl_down_sync(0xffffffffu, pre, o);
    if (lane == 0) ws[wid] = pre;
    __syncthreads();
    if (t < 32) {
        int s = ws[t];
#pragma unroll
        for (int o = 16; o > 0; o >>= 1) s += __shfl_down_sync(0xffffffffu, s, o);
        if (t == 0) sbase = s;
    }
    __syncthreads();
    int base = sbase;
    int v = hist[t];
    __syncthreads();  // ws about to be reused

    // inclusive scan of v within block
    int x = v;
#pragma unroll
    for (int o = 1; o < 32; o <<= 1) {
        int y = __shfl_up_sync(0xffffffffu, x, o);
        if (lane >= o) x += y;
    }
    if (lane == 31) ws[wid] = x;
    __syncthreads();
    if (wid == 0) {
        int s = ws[lane];
        int xs = s;
#pragma unroll
        for (int o = 1; o < 32; o <<= 1) {
            int y = __shfl_up_sync(0xffffffffu, xs, o);
            if (lane >= o) xs += y;
        }
        ws[lane] = xs - s;  // exclusive offsets of warp sums
    }
    __syncthreads();
    int incl = x + ws[wid];
    int i = lo + t;
    if (i < NN) {
        g_rowptr[i] = base + incl - v;
        g_invdeg[i] = 1.0f / fmaxf((float)v, 1.0f);
    }
    if (b == 0 && t == 0) g_rowptr[NN] = EE;
}

// ---------------- fused prep: CSR fill + x hi/lo conv + weight packing ----------------
__global__ void k_prep(const int* __restrict__ src, const int* __restrict__ dst,
                       const float* __restrict__ x,
                       const float* __restrict__ Wl, const float* __restrict__ Wr,
                       const float* __restrict__ b) {
    const int W1TN = LL * 384 * 512;
    const int W2TN = LL * 128 * 256;
    int i = blockIdx.x * blockDim.x + threadIdx.x;
    if (i < EE) {
        int d = dst[i];
        int p = atomicAdd(&g_cursor[d], 1);
        g_esrc[g_rowptr[d] + p] = src[i];
    } else if (i < EE + CONVN) {
        int j = i - EE;
        float4 v = __ldg((const float4*)x + j);
        store_split4(g_inp_h + (size_t)j * 4, g_inp_l + (size_t)j * 4, v);
    } else {
        int j = i - EE - CONVN;
        if (j < W1TN) {
            int l = j / (384 * 512);
            int rem = j % (384 * 512);
            int c = rem / 512, k = rem % 512;
            int cb = c >> 7, cc = c & 127;
            int s = k >> 7, kk = k & 127;
            float v = 0.0f;
            if (!(cb == 2 && s >= 2)) {
                int g = cb * 2 + (s >> 1);
                const float* W = (s & 1) ? Wr : Wl;
                v = W[(((size_t)l * 6 + g) * 128 + kk) * 128 + cc];
            }
            split_bf16(v, g_W1T_h[j], g_W1T_l[j]);
        } else if (j < W1TN + W2TN) {
            int j2 = j - W1TN;
            int l = j2 / (128 * 256);
            int rem = j2 % (128 * 256);
            int c = rem / 256, k = rem % 256;
            int s = k >> 7, kk = k & 127;
            const float* W = s ? Wr : Wl;
            float v = W[(((size_t)l * 6 + 5) * 128 + kk) * 128 + c];
            split_bf16(v, g_W2T_h[j2], g_W2T_l[j2]);
        } else if (j < W1TN + W2TN + LL * 384) {
            int j2 = j - W1TN - W2TN;
            int l = j2 / 384;
            int c = j2 % 384;
            int cb = c >> 7, cc = c & 127;
            g_bias[j2] = b[(((size_t)l * 6 + cb * 2) * 128) + cc] +
                         b[(((size_t)l * 6 + cb * 2 + 1) * 128) + cc];
        }
    }
}

// restore the zeroed-state invariant for the NEXT call
__global__ void k_zero_end() {
    int i = blockIdx.x * blockDim.x + threadIdx.x;
    if (i < NN) g_cursor[i] = 0;
}

// ---------------- aggregation (warp per dst node, atomic-free via CSR) ----------------
__global__ void k_agg2(const float* __restrict__ A, const float* __restrict__ B) {
    int warp = (blockIdx.x * blockDim.x + threadIdx.x) >> 5;
    int lane = threadIdx.x & 31;
    if (warp >= NN) return;
    int e = g_rowptr[warp], end = g_rowptr[warp + 1];
    float4 aa = make_float4(0.f, 0.f, 0.f, 0.f);
    float4 ab = make_float4(0.f, 0.f, 0.f, 0.f);
    // 4-edge unroll: 8 outstanding float4 gathers
    for (; e + 3 < end; e += 4) {
        int s0 = g_esrc[e], s1 = g_esrc[e + 1], s2 = g_esrc[e + 2], s3 = g_esrc[e + 3];
        float4 va0 = __ldg((const float4*)(A + (size_t)s0 * DD) + lane);
        float4 va1 = __ldg((const float4*)(A + (size_t)s1 * DD) + lane);
        float4 va2 = __ldg((const float4*)(A + (size_t)s2 * DD) + lane);
        float4 va3 = __ldg((const float4*)(A + (size_t)s3 * DD) + lane);
        float4 vb0 = __ldg((const float4*)(B + (size_t)s0 * DD) + lane);
        float4 vb1 = __ldg((const float4*)(B + (size_t)s1 * DD) + lane);
        float4 vb2 = __ldg((const float4*)(B + (size_t)s2 * DD) + lane);
        float4 vb3 = __ldg((const float4*)(B + (size_t)s3 * DD) + lane);
        aa.x += (va0.x + va1.x) + (va2.x + va3.x);
        aa.y += (va0.y + va1.y) + (va2.y + va3.y);
        aa.z += (va0.z + va1.z) + (va2.z + va3.z);
        aa.w += (va0.w + va1.w) + (va2.w + va3.w);
        ab.x += (vb0.x + vb1.x) + (vb2.x + vb3.x);
        ab.y += (vb0.y + vb1.y) + (vb2.y + vb3.y);
        ab.z += (vb0.z + vb1.z) + (vb2.z + vb3.z);
        ab.w += (vb0.w + vb1.w) + (vb2.w + vb3.w);
    }
    for (; e < end; e++) {
        int s0 = g_esrc[e];
        float4 va0 = __ldg((const float4*)(A + (size_t)s0 * DD) + lane);
        float4 vb0 = __ldg((const float4*)(B + (size_t)s0 * DD) + lane);
        aa.x += va0.x; aa.y += va0.y; aa.z += va0.z; aa.w += va0.w;
        ab.x += vb0.x; ab.y += vb0.y; ab.z += vb0.z; ab.w += vb0.w;
    }
    float sc = g_invdeg[warp];
    aa.x *= sc; aa.y *= sc; aa.z *= sc; aa.w *= sc;
    ab.x *= sc; ab.y *= sc; ab.z *= sc; ab.w *= sc;
    size_t o = (size_t)warp * DD + lane * 4;
    store_split4(g_agga_h + o, g_agga_l + o, aa);
    store_split4(g_aggb_h + o, g_aggb_l + o, ab);
    // fused: split hl row for GEMM1's h operand segment
    float4 hv = __ldg((const float4*)(B + (size_t)warp * DD) + lane);
    store_split4(g_h_h + o, g_h_l + o, hv);
}

// agg of r*h: gathers from the bf16 hi/lo pair (no fp32 RH array)
__global__ void k_agg1() {
    int warp = (blockIdx.x * blockDim.x + threadIdx.x) >> 5;
    int lane = threadIdx.x & 31;
    if (warp >= NN) return;
    int e = g_rowptr[warp], end = g_rowptr[warp + 1];
    float4 aa = make_float4(0.f, 0.f, 0.f, 0.f);
    for (; e + 1 < end; e += 2) {
        int s0 = g_esrc[e], s1 = g_esrc[e + 1];
        size_t r0 = (size_t)s0 * DD + lane * 4;
        size_t r1 = (size_t)s1 * DD + lane * 4;
        uint2 hv0 = __ldg((const uint2*)(g_rh_h + r0));
        uint2 lv0 = __ldg((const uint2*)(g_rh_l + r0));
        uint2 hv1 = __ldg((const uint2*)(g_rh_h + r1));
        uint2 lv1 = __ldg((const uint2*)(g_rh_l + r1));
        float2 a0 = __bfloat1622float2(*(__nv_bfloat162*)&hv0.x);
        float2 a1 = __bfloat1622float2(*(__nv_bfloat162*)&hv0.y);
        float2 c0 = __bfloat1622float2(*(__nv_bfloat162*)&lv0.x);
        float2 c1 = __bfloat1622float2(*(__nv_bfloat162*)&lv0.y);
        float2 b0 = __bfloat1622float2(*(__nv_bfloat162*)&hv1.x);
        float2 b1 = __bfloat1622float2(*(__nv_bfloat162*)&hv1.y);
        float2 d0 = __bfloat1622float2(*(__nv_bfloat162*)&lv1.x);
        float2 d1 = __bfloat1622float2(*(__nv_bfloat162*)&lv1.y);
        aa.x += (a0.x + c0.x) + (b0.x + d0.x);
        aa.y += (a0.y + c0.y) + (b0.y + d0.y);
        aa.z += (a1.x + c1.x) + (b1.x + d1.x);
        aa.w += (a1.y + c1.y) + (b1.y + d1.y);
    }
    if (e < end) {
        int s0 = g_esrc[e];
        size_t r0 = (size_t)s0 * DD + lane * 4;
        uint2 hv0 = __ldg((const uint2*)(g_rh_h + r0));
        uint2 lv0 = __ldg((const uint2*)(g_rh_l + r0));
        float2 a0 = __bfloat1622float2(*(__nv_bfloat162*)&hv0.x);
        float2 a1 = __bfloat1622float2(*(__nv_bfloat162*)&hv0.y);
        float2 c0 = __bfloat1622float2(*(__nv_bfloat162*)&lv0.x);
        float2 c1 = __bfloat1622float2(*(__nv_bfloat162*)&lv0.y);
        aa.x += a0.x + c0.x; aa.y += a0.y + c0.y;
        aa.z += a1.x + c1.x; aa.w += a1.y + c1.y;
    }
    float sc = g_invdeg[warp];
    aa.x *= sc; aa.y *= sc; aa.z *= sc; aa.w *= sc;
    size_t o = (size_t)warp * DD + lane * 4;
    store_split4(g_agga_h + o, g_agga_l + o, aa);
}

// ---------------- HMMA GEMM core ----------------
__device__ __forceinline__ void gemm_chunk(uint32_t sA_h, int t, float acc[2][8][4]) {
    uint32_t sA_l = sA_h + TBYTES;
    uint32_t sB_h = sA_h + 2 * TBYTES;
    uint32_t sB_l = sA_h + 3 * TBYTES;
    int lane = t & 31, wid = t >> 5;
    int wm = wid & 3, wn = wid >> 2;
    uint32_t rsel = (uint32_t)(lane & 15) * TROW + (uint32_t)(lane >> 4) * 16;

#pragma unroll
    for (int kb = 0; kb < 2; kb++) {
        uint32_t ko = kb * 32;
        uint32_t aoff = (uint32_t)(wm * 32) * TROW + rsel + ko;
        uint32_t boff = (uint32_t)(wn * 64) * TROW + rsel + ko;
        uint32_t Ah[2][4], Bh[4][4];
        ldsm4(Ah[0], sA_h + aoff);
        ldsm4(Ah[1], sA_h + aoff + 16 * TROW);
#pragma unroll
        for (int ng = 0; ng < 4; ng++) ldsm4(Bh[ng], sB_h + boff + ng * 16 * TROW);
#pragma unroll
        for (int mt = 0; mt < 2; mt++)
#pragma unroll
            for (int nt = 0; nt < 8; nt++) {
                int ng = nt >> 1, o = nt & 1;
                mma16816(acc[mt][nt], Ah[mt], Bh[ng][o], Bh[ng][o + 2]);
            }
        {
            uint32_t Bl[4][4];
#pragma unroll
            for (int ng = 0; ng < 4; ng++) ldsm4(Bl[ng], sB_l + boff + ng * 16 * TROW);
#pragma unroll
            for (int mt = 0; mt < 2; mt++)
#pragma unroll
                for (int nt = 0; nt < 8; nt++) {
                    int ng = nt >> 1, o = nt & 1;
                    mma16816(acc[mt][nt], Ah[mt], Bl[ng][o], Bl[ng][o + 2]);
                }
        }
        {
            uint32_t Al[2][4];
            ldsm4(Al[0], sA_l + aoff);
            ldsm4(Al[1], sA_l + aoff + 16 * TROW);
#pragma unroll
            for (int mt = 0; mt < 2; mt++)
#pragma unroll
                for (int nt = 0; nt < 8; nt++) {
                    int ng = nt >> 1, o = nt & 1;
                    mma16816(acc[mt][nt], Al[mt], Bh[ng][o], Bh[ng][o + 2]);
                }
        }
    }
}

// ---------------- GEMM1: [N,512]x[512,384] fused z / r*h / hx ----------------
// cb==2 (hx) uses only K-segments {agg_inp, inp}: 8 chunks instead of 16 (rest of W1 is zero).
// Single-barrier pipeline: wait -> sync -> prefetch(c+1) -> compute(c).
__global__ void __launch_bounds__(256, 2)
k_gemm1(const float* __restrict__ hl, int l) {
    extern __shared__ __align__(16) char smdyn[];
    uint32_t sb = smem_u32(smdyn);
    int t = threadIdx.x;
    int row0 = blockIdx.y * 128;
    int cb = blockIdx.x;
    int col0 = cb * 128;
    const int NC = (cb == 2) ? 8 : 16;

    const __nv_bfloat16* __restrict__ Wh = g_W1T_h + (size_t)l * 384 * 512;
    const __nv_bfloat16* __restrict__ Wlo = g_W1T_l + (size_t)l * 384 * 512;
    const __nv_bfloat16* segs_h[4] = { g_agga_h, g_inp_h, g_aggb_h, g_h_h };
    const __nv_bfloat16* segs_l[4] = { g_agga_l, g_inp_l, g_aggb_l, g_h_l };

    float acc[2][8][4];
#pragma unroll
    for (int i = 0; i < 2; i++)
#pragma unroll
        for (int j = 0; j < 8; j++)
#pragma unroll
            for (int q = 0; q < 4; q++) acc[i][j][q] = 0.0f;

    // prologue: chunk 0
    {
        uint32_t buf = sb;
        tile_async(buf,              segs_h[0], 128, row0, 0, NN, t);
        tile_async(buf + TBYTES,     segs_l[0], 128, row0, 0, NN, t);
        tile_async(buf + 2 * TBYTES, Wh,  512, col0, 0, 1 << 30, t);
        tile_async(buf + 3 * TBYTES, Wlo, 512, col0, 0, 1 << 30, t);
        CPA_COMMIT();
    }
    for (int c = 0; c < NC; c++) {
        CPA_WAIT0();          // buf[c&1] data arrived
        __syncthreads();      // + all warps finished compute(c-1) -> buf[(c+1)&1] reusable
        if (c + 1 < NC) {
            int cn = c + 1;
            int seg = cn >> 2, colA = (cn & 3) * 32, colB = cn * 32;
            uint32_t buf = sb + (cn & 1) * STAGE;
            tile_async(buf,              segs_h[seg], 128, row0, colA, NN, t);
            tile_async(buf + TBYTES,     segs_l[seg], 128, row0, colA, NN, t);
            tile_async(buf + 2 * TBYTES, Wh,  512, col0, colB, 1 << 30, t);
            tile_async(buf + 3 * TBYTES, Wlo, 512, col0, colB, 1 << 30, t);
            CPA_COMMIT();
        }
        gemm_chunk(sb + (c & 1) * STAGE, t, acc);
    }

    // epilogue
    int lane = t & 31, wid = t >> 5;
    int wm = wid & 3, wn = wid >> 2;
    const float* bias = g_bias + l * 384;
#pragma unroll
    for (int mt = 0; mt < 2; mt++)
#pragma unroll
        for (int nt = 0; nt < 8; nt++) {
            int row = row0 + wm * 32 + mt * 16 + (lane >> 2);
            int col = col0 + wn * 64 + nt * 8 + (lane & 3) * 2;
            float b0 = __ldg(bias + col), b1 = __ldg(bias + col + 1);
            int ccol = col & 127;
#pragma unroll
            for (int half = 0; half < 2; half++) {
                int r = row + half * 8;
                if (r >= NN) continue;
                float v0 = acc[mt][nt][half * 2 + 0] + b0;
                float v1 = acc[mt][nt][half * 2 + 1] + b1;
                size_t idx = (size_t)r * 128 + ccol;
                if (cb == 0) {
                    float2 z = make_float2(sigf(v0), sigf(v1));
                    *(float2*)(g_Z + idx) = z;
                } else if (cb == 1) {
                    float h0 = hl[idx], h1 = hl[idx + 1];
                    float rh0 = sigf(v0) * h0, rh1 = sigf(v1) * h1;
                    store_split2(g_rh_h + idx, g_rh_l + idx, rh0, rh1);
                } else {
                    *(float2*)(g_HX + idx) = make_float2(v0, v1);
                }
            }
        }
}

// ---------------- GEMM2: [N,256]x[256,128] fused GRU mix ----------------
__global__ void __launch_bounds__(256, 2)
k_gemm2(const float* __restrict__ hl, float* __restrict__ out, int l) {
    extern __shared__ __align__(16) char smdyn[];
    uint32_t sb = smem_u32(smdyn);
    int t = threadIdx.x;
    int row0 = blockIdx.y * 128;

    const __nv_bfloat16* __restrict__ Wh = g_W2T_h + (size_t)l * 128 * 256;
    const __nv_bfloat16* __restrict__ Wlo = g_W2T_l + (size_t)l * 128 * 256;
    const __nv_bfloat16* segs_h[2] = { g_agga_h, g_rh_h };
    const __nv_bfloat16* segs_l[2] = { g_agga_l, g_rh_l };

    float acc[2][8][4];
#pragma unroll
    for (int i = 0; i < 2; i++)
#pragma unroll
        for (int j = 0; j < 8; j++)
#pragma unroll
            for (int q = 0; q < 4; q++) acc[i][j][q] = 0.0f;

    {
        uint32_t buf = sb;
        tile_async(buf,              segs_h[0], 128, row0, 0, NN, t);
        tile_async(buf + TBYTES,     segs_l[0], 128, row0, 0, NN, t);
        tile_async(buf + 2 * TBYTES, Wh,  256, 0, 0, 1 << 30, t);
        tile_async(buf + 3 * TBYTES, Wlo, 256, 0, 0, 1 << 30, t);
        CPA_COMMIT();
    }
    for (int c = 0; c < 8; c++) {
        CPA_WAIT0();
        __syncthreads();
        if (c + 1 < 8) {
            int cn = c + 1;
            int seg = cn >> 2, colA = (cn & 3) * 32, colB = cn * 32;
            uint32_t buf = sb + (cn & 1) * STAGE;
            tile_async(buf,              segs_h[seg], 128, row0, colA, NN, t);
            tile_async(buf + TBYTES,     segs_l[seg], 128, row0, colA, NN, t);
            tile_async(buf + 2 * TBYTES, Wh,  256, 0, colB, 1 << 30, t);
            tile_async(buf + 3 * TBYTES, Wlo, 256, 0, colB, 1 << 30, t);
            CPA_COMMIT();
        }
        gemm_chunk(sb + (c & 1) * STAGE, t, acc);
    }

    int lane = t & 31, wid = t >> 5;
    int wm = wid & 3, wn = wid >> 2;
#pragma unroll
    for (int mt = 0; mt < 2; mt++)
#pragma unroll
        for (int nt = 0; nt < 8; nt++) {
            int row = row0 + wm * 32 + mt * 16 + (lane >> 2);
            int col = wn * 64 + nt * 8 + (lane & 3) * 2;
#pragma unroll
            for (int half = 0; half < 2; half++) {
                int r = row + half * 8;
                if (r >= NN) continue;
                size_t idx = (size_t)r * 128 + col;
                float hx0 = g_HX[idx], hx1 = g_HX[idx + 1];
                float z0 = g_Z[idx], z1 = g_Z[idx + 1];
                float h0 = hl[idx], h1 = hl[idx + 1];
                float ht0 = tanhf(acc[mt][nt][half * 2 + 0] + hx0);
                float ht1 = tanhf(acc[mt][nt][half * 2 + 1] + hx1);
                float o0 = z0 * h0 + (1.0f - z0) * ht0;
                float o1 = z1 * h1 + (1.0f - z1) * ht1;
                *(float2*)(out + idx) = make_float2(o0, o1);
                store_split2(g_inp_h + idx, g_inp_l + idx, o0, o1);
            }
        }
}

// ---------------- launch ----------------
extern "C" void kernel_launch(void* const* d_in, const int* in_sizes, int n_in,
                              void* d_out, int out_size) {
    const float* x  = (const float*)d_in[0];
    const float* h  = (const float*)d_in[1];
    const float* Wl = (const float*)d_in[2];
    const float* Wr = (const float*)d_in[3];
    const float* b  = (const float*)d_in[4];
    const int* src  = (const int*)d_in[5];
    const int* dst  = (const int*)d_in[6];
    float* out = (float*)d_out;

    cudaFuncSetAttribute(k_gemm1, cudaFuncAttributeMaxDynamicSharedMemorySize, GSMEM);
    cudaFuncSetAttribute(k_gemm2, cudaFuncAttributeMaxDynamicSharedMemorySize, GSMEM);

    const int ROWT = (NN + 127) / 128;
    const int WTOT = LL * 384 * 512 + LL * 128 * 256 + LL * 384;
    const int PREPN = EE + CONVN + WTOT;

    // (1) CSR count+scan  (2) fill + x-conv + weights  (g_cursor arrives zeroed)
    k_countscan<<<NCHUNK, 1024>>>(dst);
    k_prep<<<(PREPN + 255) / 256, 256>>>(src, dst, x, Wl, Wr, b);

    for (int l = 0; l < LL; l++) {
        const float* hl = h + (size_t)l * NN * DD;
        k_agg2<<<(NN * 32 + 255) / 256, 256>>>(
            (l == 0) ? x : (out + (size_t)(l - 1) * NN * DD), hl);  // (3)
        dim3 g1(3, ROWT);
        k_gemm1<<<g1, 256, GSMEM>>>(hl, l);                          // (4) <- ncu target
        k_agg1<<<(NN * 32 + 255) / 256, 256>>>();
        dim3 g2(1, ROWT);
        k_gemm2<<<g2, 256, GSMEM>>>(hl, out + (size_t)l * NN * DD, l);
    }

    // restore zeroed-state invariant for the next call
    k_zero_end<<<(NN + 255) / 256, 256>>>();
}

// round 10
// speedup vs baseline: 1.0058x; 1.0058x over previous
#include <cuda_runtime.h>
#include <cuda_bf16.h>
#include <math.h>
#include <stdint.h>

// Problem constants (fixed by setup_inputs)
#define NN 50000
#define EE 800000
#define DD 128
#define LL 2
#define NCHUNK ((NN + 1023) / 1024)
#define CONVN (NN * DD / 4)

// ---------------- scratch (static __device__ globals; no allocation) ----------------
// g_cursor is zeroed by k_zero_end at the END of each launch (module-load zero-init
// covers the first call).
__device__ float g_Z[NN * DD];
__device__ float g_HX[NN * DD];
__device__ float g_bias[LL * 384];
__device__ float g_invdeg[NN];
__device__ int g_rowptr[NN + 1];
__device__ int g_cursor[NN];
__device__ int g_esrc[EE];

__device__ __align__(16) __nv_bfloat16 g_inp_h[NN * DD], g_inp_l[NN * DD];
__device__ __align__(16) __nv_bfloat16 g_h_h[NN * DD],   g_h_l[NN * DD];
__device__ __align__(16) __nv_bfloat16 g_agga_h[NN * DD], g_agga_l[NN * DD];
__device__ __align__(16) __nv_bfloat16 g_aggb_h[NN * DD], g_aggb_l[NN * DD];
__device__ __align__(16) __nv_bfloat16 g_rh_h[NN * DD],  g_rh_l[NN * DD];
__device__ __align__(16) __nv_bfloat16 g_W1T_h[LL * 384 * 512], g_W1T_l[LL * 384 * 512];
__device__ __align__(16) __nv_bfloat16 g_W2T_h[LL * 128 * 256], g_W2T_l[LL * 128 * 256];

// ---------------- helpers ----------------
__device__ __forceinline__ uint32_t smem_u32(const void* p) {
    uint32_t a;
    asm("{ .reg .u64 t; cvta.to.shared.u64 t, %1; cvt.u32.u64 %0, t; }" : "=r"(a) : "l"(p));
    return a;
}
__device__ __forceinline__ void ldsm4(uint32_t* f, uint32_t addr) {
    asm volatile("ldmatrix.sync.aligned.m8n8.x4.shared.b16 {%0,%1,%2,%3}, [%4];"
                 : "=r"(f[0]), "=r"(f[1]), "=r"(f[2]), "=r"(f[3]) : "r"(addr));
}
__device__ __forceinline__ void mma16816(float* c, const uint32_t* a, uint32_t b0, uint32_t b1) {
    asm volatile(
        "mma.sync.aligned.m16n8k16.row.col.f32.bf16.bf16.f32 "
        "{%0,%1,%2,%3}, {%4,%5,%6,%7}, {%8,%9}, {%0,%1,%2,%3};"
        : "+f"(c[0]), "+f"(c[1]), "+f"(c[2]), "+f"(c[3])
        : "r"(a[0]), "r"(a[1]), "r"(a[2]), "r"(a[3]), "r"(b0), "r"(b1));
}
__device__ __forceinline__ void cpa16(uint32_t dst, const void* src, int sz) {
    asm volatile("cp.async.cg.shared.global [%0], [%1], 16, %2;"
                 :: "r"(dst), "l"(src), "r"(sz) : "memory");
}
#define CPA_COMMIT() asm volatile("cp.async.commit_group;" ::: "memory")
#define CPA_WAIT0()  asm volatile("cp.async.wait_group 0;" ::: "memory")

__device__ __forceinline__ void split_bf16(float v, __nv_bfloat16& h, __nv_bfloat16& l) {
    h = __float2bfloat16(v);
    l = __float2bfloat16(v - __bfloat162float(h));
}
__device__ __forceinline__ void store_split4(__nv_bfloat16* dh, __nv_bfloat16* dl, float4 v) {
    union { __nv_bfloat16 b[4]; unsigned long long u; } H, L;
    split_bf16(v.x, H.b[0], L.b[0]);
    split_bf16(v.y, H.b[1], L.b[1]);
    split_bf16(v.z, H.b[2], L.b[2]);
    split_bf16(v.w, H.b[3], L.b[3]);
    *(unsigned long long*)dh = H.u;
    *(unsigned long long*)dl = L.u;
}
__device__ __forceinline__ void store_split2(__nv_bfloat16* dh, __nv_bfloat16* dl, float a, float b) {
    union { __nv_bfloat16 b2[2]; uint32_t u; } H, L;
    split_bf16(a, H.b2[0], L.b2[0]);
    split_bf16(b, H.b2[1], L.b2[1]);
    *(uint32_t*)dh = H.u;
    *(uint32_t*)dl = L.u;
}
__device__ __forceinline__ float sigf(float x) { return 1.0f / (1.0f + expf(-x)); }

// SMEM tile geometry: 128 rows x 32 bf16, padded row stride 80B (conflict-free ldmatrix)
#define TROW 80
#define TBYTES (128 * TROW)        // 10240
#define STAGE (4 * TBYTES)         // Ah,Al,Bh,Bl
#define GSMEM (2 * STAGE)          // 81920

// precomputed per-thread tile-load state (addresses hoisted out of the chunk loop)
struct Pre {
    uint32_t sm0, sm1;       // smem offsets within a tile
    size_t a0, a1;           // A-side global element offsets (row*128 + q*8)
    int az0, az1;            // A-side cp sizes (16 or 0 for OOB rows)
    size_t b0, b1;           // B-side global element offsets (row*strideB + q*8)
};

__device__ __forceinline__ void load_stage(uint32_t buf,
                                           const __nv_bfloat16* __restrict__ ah,
                                           const __nv_bfloat16* __restrict__ al,
                                           const __nv_bfloat16* __restrict__ bh,
                                           const __nv_bfloat16* __restrict__ bl,
                                           int colA, int colB, const Pre& p) {
    cpa16(buf + p.sm0,              ah + p.a0 + colA, p.az0);
    cpa16(buf + p.sm1,              ah + p.a1 + colA, p.az1);
    cpa16(buf + TBYTES + p.sm0,     al + p.a0 + colA, p.az0);
    cpa16(buf + TBYTES + p.sm1,     al + p.a1 + colA, p.az1);
    cpa16(buf + 2 * TBYTES + p.sm0, bh + p.b0 + colB, 16);
    cpa16(buf + 2 * TBYTES + p.sm1, bh + p.b1 + colB, 16);
    cpa16(buf + 3 * TBYTES + p.sm0, bl + p.b0 + colB, 16);
    cpa16(buf + 3 * TBYTES + p.sm1, bl + p.b1 + colB, 16);
}

__device__ __forceinline__ Pre make_pre(int t, int row0, int col0, int strideB) {
    Pre p;
    int q = t & 3;
    int r0 = t >> 2, r1 = r0 + 64;
    p.sm0 = (uint32_t)(r0 * TROW + q * 16);
    p.sm1 = (uint32_t)(r1 * TROW + q * 16);
    int gr0 = row0 + r0, gr1 = row0 + r1;
    p.az0 = gr0 < NN ? 16 : 0;
    p.az1 = gr1 < NN ? 16 : 0;
    if (gr0 >= NN) gr0 = 0;
    if (gr1 >= NN) gr1 = 0;
    p.a0 = (size_t)gr0 * 128 + q * 8;
    p.a1 = (size_t)gr1 * 128 + q * 8;
    p.b0 = (size_t)(col0 + r0) * strideB + q * 8;
    p.b1 = (size_t)(col0 + r1) * strideB + q * 8;
    return p;
}

// ---------------- CSR: fused count+scan ----------------
__global__ void __launch_bounds__(1024)
k_countscan(const int* __restrict__ dst) {
    __shared__ int hist[1024];
    __shared__ int ws[32];
    __shared__ int sbase;
    int b = blockIdx.x, t = threadIdx.x;
    int lane = t & 31, wid = t >> 5;
    hist[t] = 0;
    __syncthreads();

    int lo = b << 10;
    int pre = 0;
    const int4* d4 = (const int4*)dst;
    for (int e = t; e < EE / 4; e += 1024) {
        int4 v = __ldg(d4 + e);
        pre += (v.x < lo) + (v.y < lo) + (v.z < lo) + (v.w < lo);
        int dx;
        dx = v.x - lo; if ((unsigned)dx < 1024u) atomicAdd(&hist[dx], 1);
        dx = v.y - lo; if ((unsigned)dx < 1024u) atomicAdd(&hist[dx], 1);
        dx = v.z - lo; if ((unsigned)dx < 1024u) atomicAdd(&hist[dx], 1);
        dx = v.w - lo; if ((unsigned)dx < 1024u) atomicAdd(&hist[dx], 1);
    }
#pragma unroll
    for (int o = 16; o > 0; o >>= 1) pre += __shfl_down_sync(0xffffffffu, pre, o);
    if (lane == 0) ws[wid] = pre;
    __syncthreads();
    if (t < 32) {
        int s = ws[t];
#pragma unroll
        for (int o = 16; o > 0; o >>= 1) s += __shfl_down_sync(0xffffffffu, s, o);
        if (t == 0) sbase = s;
    }
    __syncthreads();
    int base = sbase;
    int v = hist[t];
    __syncthreads();

    int x = v;
#pragma unroll
    for (int o = 1; o < 32; o <<= 1) {
        int y = __shfl_up_sync(0xffffffffu, x, o);
        if (lane >= o) x += y;
    }
    if (lane == 31) ws[wid] = x;
    __syncthreads();
    if (wid == 0) {
        int s = ws[lane];
        int xs = s;
#pragma unroll
        for (int o = 1; o < 32; o <<= 1) {
            int y = __shfl_up_sync(0xffffffffu, xs, o);
            if (lane >= o) xs += y;
        }
        ws[lane] = xs - s;
    }
    __syncthreads();
    int incl = x + ws[wid];
    int i = lo + t;
    if (i < NN) {
        g_rowptr[i] = base + incl - v;
        g_invdeg[i] = 1.0f / fmaxf((float)v, 1.0f);
    }
    if (b == 0 && t == 0) g_rowptr[NN] = EE;
}

// ---------------- fused prep: CSR fill + x hi/lo conv + weight packing ----------------
__global__ void k_prep(const int* __restrict__ src, const int* __restrict__ dst,
                       const float* __restrict__ x,
                       const float* __restrict__ Wl, const float* __restrict__ Wr,
                       const float* __restrict__ b) {
    const int W1TN = LL * 384 * 512;
    const int W2TN = LL * 128 * 256;
    int i = blockIdx.x * blockDim.x + threadIdx.x;
    if (i < EE) {
        int d = dst[i];
        int p = atomicAdd(&g_cursor[d], 1);
        g_esrc[g_rowptr[d] + p] = src[i];
    } else if (i < EE + CONVN) {
        int j = i - EE;
        float4 v = __ldg((const float4*)x + j);
        store_split4(g_inp_h + (size_t)j * 4, g_inp_l + (size_t)j * 4, v);
    } else {
        int j = i - EE - CONVN;
        if (j < W1TN) {
            int l = j / (384 * 512);
            int rem = j % (384 * 512);
            int c = rem / 512, k = rem % 512;
            int cb = c >> 7, cc = c & 127;
            int s = k >> 7, kk = k & 127;
            float v = 0.0f;
            if (!(cb == 2 && s >= 2)) {
                int g = cb * 2 + (s >> 1);
                const float* W = (s & 1) ? Wr : Wl;
                v = W[(((size_t)l * 6 + g) * 128 + kk) * 128 + cc];
            }
            split_bf16(v, g_W1T_h[j], g_W1T_l[j]);
        } else if (j < W1TN + W2TN) {
            int j2 = j - W1TN;
            int l = j2 / (128 * 256);
            int rem = j2 % (128 * 256);
            int c = rem / 256, k = rem % 256;
            int s = k >> 7, kk = k & 127;
            const float* W = s ? Wr : Wl;
            float v = W[(((size_t)l * 6 + 5) * 128 + kk) * 128 + c];
            split_bf16(v, g_W2T_h[j2], g_W2T_l[j2]);
        } else if (j < W1TN + W2TN + LL * 384) {
            int j2 = j - W1TN - W2TN;
            int l = j2 / 384;
            int c = j2 % 384;
            int cb = c >> 7, cc = c & 127;
            g_bias[j2] = b[(((size_t)l * 6 + cb * 2) * 128) + cc] +
                         b[(((size_t)l * 6 + cb * 2 + 1) * 128) + cc];
        }
    }
}

__global__ void k_zero_end() {
    int i = blockIdx.x * blockDim.x + threadIdx.x;
    if (i < NN) g_cursor[i] = 0;
}

// ---------------- aggregation (warp per dst node, atomic-free via CSR) ----------------
__global__ void k_agg2(const float* __restrict__ A, const float* __restrict__ B) {
    int warp = (blockIdx.x * blockDim.x + threadIdx.x) >> 5;
    int lane = threadIdx.x & 31;
    if (warp >= NN) return;
    int e = g_rowptr[warp], end = g_rowptr[warp + 1];
    float4 aa = make_float4(0.f, 0.f, 0.f, 0.f);
    float4 ab = make_float4(0.f, 0.f, 0.f, 0.f);
    for (; e + 3 < end; e += 4) {
        int s0 = g_esrc[e], s1 = g_esrc[e + 1], s2 = g_esrc[e + 2], s3 = g_esrc[e + 3];
        float4 va0 = __ldg((const float4*)(A + (size_t)s0 * DD) + lane);
        float4 va1 = __ldg((const float4*)(A + (size_t)s1 * DD) + lane);
        float4 va2 = __ldg((const float4*)(A + (size_t)s2 * DD) + lane);
        float4 va3 = __ldg((const float4*)(A + (size_t)s3 * DD) + lane);
        float4 vb0 = __ldg((const float4*)(B + (size_t)s0 * DD) + lane);
        float4 vb1 = __ldg((const float4*)(B + (size_t)s1 * DD) + lane);
        float4 vb2 = __ldg((const float4*)(B + (size_t)s2 * DD) + lane);
        float4 vb3 = __ldg((const float4*)(B + (size_t)s3 * DD) + lane);
        aa.x += (va0.x + va1.x) + (va2.x + va3.x);
        aa.y += (va0.y + va1.y) + (va2.y + va3.y);
        aa.z += (va0.z + va1.z) + (va2.z + va3.z);
        aa.w += (va0.w + va1.w) + (va2.w + va3.w);
        ab.x += (vb0.x + vb1.x) + (vb2.x + vb3.x);
        ab.y += (vb0.y + vb1.y) + (vb2.y + vb3.y);
        ab.z += (vb0.z + vb1.z) + (vb2.z + vb3.z);
        ab.w += (vb0.w + vb1.w) + (vb2.w + vb3.w);
    }
    for (; e < end; e++) {
        int s0 = g_esrc[e];
        float4 va0 = __ldg((const float4*)(A + (size_t)s0 * DD) + lane);
        float4 vb0 = __ldg((const float4*)(B + (size_t)s0 * DD) + lane);
        aa.x += va0.x; aa.y += va0.y; aa.z += va0.z; aa.w += va0.w;
        ab.x += vb0.x; ab.y += vb0.y; ab.z += vb0.z; ab.w += vb0.w;
    }
    float sc = g_invdeg[warp];
    aa.x *= sc; aa.y *= sc; aa.z *= sc; aa.w *= sc;
    ab.x *= sc; ab.y *= sc; ab.z *= sc; ab.w *= sc;
    size_t o = (size_t)warp * DD + lane * 4;
    store_split4(g_agga_h + o, g_agga_l + o, aa);
    store_split4(g_aggb_h + o, g_aggb_l + o, ab);
    float4 hv = __ldg((const float4*)(B + (size_t)warp * DD) + lane);
    store_split4(g_h_h + o, g_h_l + o, hv);
}

__global__ void k_agg1() {
    int warp = (blockIdx.x * blockDim.x + threadIdx.x) >> 5;
    int lane = threadIdx.x & 31;
    if (warp >= NN) return;
    int e = g_rowptr[warp], end = g_rowptr[warp + 1];
    float4 aa = make_float4(0.f, 0.f, 0.f, 0.f);
    for (; e + 1 < end; e += 2) {
        int s0 = g_esrc[e], s1 = g_esrc[e + 1];
        size_t r0 = (size_t)s0 * DD + lane * 4;
        size_t r1 = (size_t)s1 * DD + lane * 4;
        uint2 hv0 = __ldg((const uint2*)(g_rh_h + r0));
        uint2 lv0 = __ldg((const uint2*)(g_rh_l + r0));
        uint2 hv1 = __ldg((const uint2*)(g_rh_h + r1));
        uint2 lv1 = __ldg((const uint2*)(g_rh_l + r1));
        float2 a0 = __bfloat1622float2(*(__nv_bfloat162*)&hv0.x);
        float2 a1 = __bfloat1622float2(*(__nv_bfloat162*)&hv0.y);
        float2 c0 = __bfloat1622float2(*(__nv_bfloat162*)&lv0.x);
        float2 c1 = __bfloat1622float2(*(__nv_bfloat162*)&lv0.y);
        float2 b0 = __bfloat1622float2(*(__nv_bfloat162*)&hv1.x);
        float2 b1 = __bfloat1622float2(*(__nv_bfloat162*)&hv1.y);
        float2 d0 = __bfloat1622float2(*(__nv_bfloat162*)&lv1.x);
        float2 d1 = __bfloat1622float2(*(__nv_bfloat162*)&lv1.y);
        aa.x += (a0.x + c0.x) + (b0.x + d0.x);
        aa.y += (a0.y + c0.y) + (b0.y + d0.y);
        aa.z += (a1.x + c1.x) + (b1.x + d1.x);
        aa.w += (a1.y + c1.y) + (b1.y + d1.y);
    }
    if (e < end) {
        int s0 = g_esrc[e];
        size_t r0 = (size_t)s0 * DD + lane * 4;
        uint2 hv0 = __ldg((const uint2*)(g_rh_h + r0));
        uint2 lv0 = __ldg((const uint2*)(g_rh_l + r0));
        float2 a0 = __bfloat1622float2(*(__nv_bfloat162*)&hv0.x);
        float2 a1 = __bfloat1622float2(*(__nv_bfloat162*)&hv0.y);
        float2 c0 = __bfloat1622float2(*(__nv_bfloat162*)&lv0.x);
        float2 c1 = __bfloat1622float2(*(__nv_bfloat162*)&lv0.y);
        aa.x += a0.x + c0.x; aa.y += a0.y + c0.y;
        aa.z += a1.x + c1.x; aa.w += a1.y + c1.y;
    }
    float sc = g_invdeg[warp];
    aa.x *= sc; aa.y *= sc; aa.z *= sc; aa.w *= sc;
    size_t o = (size_t)warp * DD + lane * 4;
    store_split4(g_agga_h + o, g_agga_l + o, aa);
}

// ---------------- HMMA GEMM core: fragments-first schedule, hoisted offsets ----------------
__device__ __forceinline__ void gemm_chunk(uint32_t sA_h, uint32_t lsm_a, uint32_t lsm_b,
                                           float acc[2][8][4]) {
    uint32_t sA_l = sA_h + TBYTES;
    uint32_t sB_h = sA_h + 2 * TBYTES;
    uint32_t sB_l = sA_h + 3 * TBYTES;
#pragma unroll
    for (int kb = 0; kb < 2; kb++) {
        uint32_t ko = kb * 32;
        uint32_t aoff = lsm_a + ko;
        uint32_t boff = lsm_b + ko;
        uint32_t Ah[2][4], Al[2][4], Bh[4][4], Bl[4][4];
        // all 12 ldsm4 up front: max LDS MLP, no mid-pass bubbles
        ldsm4(Ah[0], sA_h + aoff);
        ldsm4(Ah[1], sA_h + aoff + 16 * TROW);
#pragma unroll
        for (int ng = 0; ng < 4; ng++) ldsm4(Bh[ng], sB_h + boff + ng * 16 * TROW);
#pragma unroll
        for (int ng = 0; ng < 4; ng++) ldsm4(Bl[ng], sB_l + boff + ng * 16 * TROW);
        ldsm4(Al[0], sA_l + aoff);
        ldsm4(Al[1], sA_l + aoff + 16 * TROW);
        // 48 MMAs back-to-back
#pragma unroll
        for (int mt = 0; mt < 2; mt++)
#pragma unroll
            for (int nt = 0; nt < 8; nt++) {
                int ng = nt >> 1, o = nt & 1;
                mma16816(acc[mt][nt], Ah[mt], Bh[ng][o], Bh[ng][o + 2]);
            }
#pragma unroll
        for (int mt = 0; mt < 2; mt++)
#pragma unroll
            for (int nt = 0; nt < 8; nt++) {
                int ng = nt >> 1, o = nt & 1;
                mma16816(acc[mt][nt], Ah[mt], Bl[ng][o], Bl[ng][o + 2]);
            }
#pragma unroll
        for (int mt = 0; mt < 2; mt++)
#pragma unroll
            for (int nt = 0; nt < 8; nt++) {
                int ng = nt >> 1, o = nt & 1;
                mma16816(acc[mt][nt], Al[mt], Bh[ng][o], Bh[ng][o + 2]);
            }
    }
}

// ---------------- GEMM1: [N,512]x[512,384] fused z / r*h / hx ----------------
__global__ void __launch_bounds__(256, 2)
k_gemm1(const float* __restrict__ hl, int l) {
    extern __shared__ __align__(16) char smdyn[];
    uint32_t sb = smem_u32(smdyn);
    int t = threadIdx.x;
    int row0 = blockIdx.y * 128;
    int cb = blockIdx.x;
    int col0 = cb * 128;
    const int NC = (cb == 2) ? 8 : 16;

    const __nv_bfloat16* __restrict__ Wh = g_W1T_h + (size_t)l * 384 * 512;
    const __nv_bfloat16* __restrict__ Wlo = g_W1T_l + (size_t)l * 384 * 512;
    const __nv_bfloat16* segs_h[4] = { g_agga_h, g_inp_h, g_aggb_h, g_h_h };
    const __nv_bfloat16* segs_l[4] = { g_agga_l, g_inp_l, g_aggb_l, g_h_l };

    const Pre p = make_pre(t, row0, col0, 512);
    int lane = t & 31, wid = t >> 5;
    int wm = wid & 3, wn = wid >> 2;
    uint32_t rsel = (uint32_t)(lane & 15) * TROW + (uint32_t)(lane >> 4) * 16;
    uint32_t lsm_a = (uint32_t)(wm * 32) * TROW + rsel;
    uint32_t lsm_b = (uint32_t)(wn * 64) * TROW + rsel;

    float acc[2][8][4];
#pragma unroll
    for (int i = 0; i < 2; i++)
#pragma unroll
        for (int j = 0; j < 8; j++)
#pragma unroll
            for (int q = 0; q < 4; q++) acc[i][j][q] = 0.0f;

    load_stage(sb, segs_h[0], segs_l[0], Wh, Wlo, 0, 0, p);
    CPA_COMMIT();
    for (int c = 0; c < NC; c++) {
        CPA_WAIT0();
        __syncthreads();
        if (c + 1 < NC) {
            int cn = c + 1;
            int seg = cn >> 2, colA = (cn & 3) * 32, colB = cn * 32;
            load_stage(sb + (cn & 1) * STAGE, segs_h[seg], segs_l[seg], Wh, Wlo, colA, colB, p);
            CPA_COMMIT();
        }
        gemm_chunk(sb + (c & 1) * STAGE, lsm_a, lsm_b, acc);
    }

    // epilogue
    const float* bias = g_bias + l * 384;
#pragma unroll
    for (int mt = 0; mt < 2; mt++)
#pragma unroll
        for (int nt = 0; nt < 8; nt++) {
            int row = row0 + wm * 32 + mt * 16 + (lane >> 2);
            int col = col0 + wn * 64 + nt * 8 + (lane & 3) * 2;
            float b0 = __ldg(bias + col), b1 = __ldg(bias + col + 1);
            int ccol = col & 127;
#pragma unroll
            for (int half = 0; half < 2; half++) {
                int r = row + half * 8;
                if (r >= NN) continue;
                float v0 = acc[mt][nt][half * 2 + 0] + b0;
                float v1 = acc[mt][nt][half * 2 + 1] + b1;
                size_t idx = (size_t)r * 128 + ccol;
                if (cb == 0) {
                    float2 z = make_float2(sigf(v0), sigf(v1));
                    *(float2*)(g_Z + idx) = z;
                } else if (cb == 1) {
                    float h0 = hl[idx], h1 = hl[idx + 1];
                    float rh0 = sigf(v0) * h0, rh1 = sigf(v1) * h1;
                    store_split2(g_rh_h + idx, g_rh_l + idx, rh0, rh1);
                } else {
                    *(float2*)(g_HX + idx) = make_float2(v0, v1);
                }
            }
        }
}

// ---------------- GEMM2: [N,256]x[256,128] fused GRU mix ----------------
__global__ void __launch_bounds__(256, 2)
k_gemm2(const float* __restrict__ hl, float* __restrict__ out, int l) {
    extern __shared__ __align__(16) char smdyn[];
    uint32_t sb = smem_u32(smdyn);
    int t = threadIdx.x;
    int row0 = blockIdx.y * 128;

    const __nv_bfloat16* __restrict__ Wh = g_W2T_h + (size_t)l * 128 * 256;
    const __nv_bfloat16* __restrict__ Wlo = g_W2T_l + (size_t)l * 128 * 256;
    const __nv_bfloat16* segs_h[2] = { g_agga_h, g_rh_h };
    const __nv_bfloat16* segs_l[2] = { g_agga_l, g_rh_l };

    const Pre p = make_pre(t, row0, 0, 256);
    int lane = t & 31, wid = t >> 5;
    int wm = wid & 3, wn = wid >> 2;
    uint32_t rsel = (uint32_t)(lane & 15) * TROW + (uint32_t)(lane >> 4) * 16;
    uint32_t lsm_a = (uint32_t)(wm * 32) * TROW + rsel;
    uint32_t lsm_b = (uint32_t)(wn * 64) * TROW + rsel;

    float acc[2][8][4];
#pragma unroll
    for (int i = 0; i < 2; i++)
#pragma unroll
        for (int j = 0; j < 8; j++)
#pragma unroll
            for (int q = 0; q < 4; q++) acc[i][j][q] = 0.0f;

    load_stage(sb, segs_h[0], segs_l[0], Wh, Wlo, 0, 0, p);
    CPA_COMMIT();
    for (int c = 0; c < 8; c++) {
        CPA_WAIT0();
        __syncthreads();
        if (c + 1 < 8) {
            int cn = c + 1;
            int seg = cn >> 2, colA = (cn & 3) * 32, colB = cn * 32;
            load_stage(sb + (cn & 1) * STAGE, segs_h[seg], segs_l[seg], Wh, Wlo, colA, colB, p);
            CPA_COMMIT();
        }
        gemm_chunk(sb + (c & 1) * STAGE, lsm_a, lsm_b, acc);
    }

#pragma unroll
    for (int mt = 0; mt < 2; mt++)
#pragma unroll
        for (int nt = 0; nt < 8; nt++) {
            int row = row0 + wm * 32 + mt * 16 + (lane >> 2);
            int col = wn * 64 + nt * 8 + (lane & 3) * 2;
#pragma unroll
            for (int half = 0; half < 2; half++) {
                int r = row + half * 8;
                if (r >= NN) continue;
                size_t idx = (size_t)r * 128 + col;
                float hx0 = g_HX[idx], hx1 = g_HX[idx + 1];
                float z0 = g_Z[idx], z1 = g_Z[idx + 1];
                float h0 = hl[idx], h1 = hl[idx + 1];
                float ht0 = tanhf(acc[mt][nt][half * 2 + 0] + hx0);
                float ht1 = tanhf(acc[mt][nt][half * 2 + 1] + hx1);
                float o0 = z0 * h0 + (1.0f - z0) * ht0;
                float o1 = z1 * h1 + (1.0f - z1) * ht1;
                *(float2*)(out + idx) = make_float2(o0, o1);
                store_split2(g_inp_h + idx, g_inp_l + idx, o0, o1);
            }
        }
}

// ---------------- launch ----------------
extern "C" void kernel_launch(void* const* d_in, const int* in_sizes, int n_in,
                              void* d_out, int out_size) {
    const float* x  = (const float*)d_in[0];
    const float* h  = (const float*)d_in[1];
    const float* Wl = (const float*)d_in[2];
    const float* Wr = (const float*)d_in[3];
    const float* b  = (const float*)d_in[4];
    const int* src  = (const int*)d_in[5];
    const int* dst  = (const int*)d_in[6];
    float* out = (float*)d_out;

    cudaFuncSetAttribute(k_gemm1, cudaFuncAttributeMaxDynamicSharedMemorySize, GSMEM);
    cudaFuncSetAttribute(k_gemm2, cudaFuncAttributeMaxDynamicSharedMemorySize, GSMEM);

    const int ROWT = (NN + 127) / 128;
    const int WTOT = LL * 384 * 512 + LL * 128 * 256 + LL * 384;
    const int PREPN = EE + CONVN + WTOT;

    k_countscan<<<NCHUNK, 1024>>>(dst);
    k_prep<<<(PREPN + 255) / 256, 256>>>(src, dst, x, Wl, Wr, b);

    for (int l = 0; l < LL; l++) {
        const float* hl = h + (size_t)l * NN * DD;
        k_agg2<<<(NN * 32 + 255) / 256, 256>>>(
            (l == 0) ? x : (out + (size_t)(l - 1) * NN * DD), hl);
        dim3 g1(3, ROWT);
        k_gemm1<<<g1, 256, GSMEM>>>(hl, l);   // launch #4 <- ncu target
        k_agg1<<<(NN * 32 + 255) / 256, 256>>>();
        dim3 g2(1, ROWT);
        k_gemm2<<<g2, 256, GSMEM>>>(hl, out + (size_t)l * NN * DD, l);
    }

    k_zero_end<<<(NN + 255) / 256, 256>>>();
}

// round 11
// speedup vs baseline: 1.5240x; 1.5151x over previous
#include <cuda_runtime.h>
#include <cuda_fp16.h>
#include <math.h>
#include <stdint.h>

// Problem constants (fixed by setup_inputs)
#define NN 50000
#define EE 800000
#define DD 128
#define LL 2
#define NCHUNK ((NN + 1023) / 1024)
#define CONVN (NN * DD / 4)

// ---------------- scratch (static __device__ globals; no allocation) ----------------
// g_cursor is zeroed by k_zero_end at the END of each launch (module-load zero-init
// covers the first call).
__device__ float g_Z[NN * DD];
__device__ float g_HX[NN * DD];
__device__ float g_bias[LL * 384];
__device__ float g_invdeg[NN];
__device__ int g_rowptr[NN + 1];
__device__ int g_cursor[NN];
__device__ int g_esrc[EE];

// single-precision-fp16 operands (single-pass HMMA; error model validated R5-R10)
__device__ __align__(16) __half g_inp[NN * DD];
__device__ __align__(16) __half g_h[NN * DD];
__device__ __align__(16) __half g_agga[NN * DD];
__device__ __align__(16) __half g_aggb[NN * DD];
__device__ __align__(16) __half g_rh[NN * DD];
__device__ __align__(16) __half g_W1T[LL * 384 * 512];
__device__ __align__(16) __half g_W2T[LL * 128 * 256];

// ---------------- helpers ----------------
__device__ __forceinline__ uint32_t smem_u32(const void* p) {
    uint32_t a;
    asm("{ .reg .u64 t; cvta.to.shared.u64 t, %1; cvt.u32.u64 %0, t; }" : "=r"(a) : "l"(p));
    return a;
}
__device__ __forceinline__ void ldsm4(uint32_t* f, uint32_t addr) {
    asm volatile("ldmatrix.sync.aligned.m8n8.x4.shared.b16 {%0,%1,%2,%3}, [%4];"
                 : "=r"(f[0]), "=r"(f[1]), "=r"(f[2]), "=r"(f[3]) : "r"(addr));
}
__device__ __forceinline__ void mma16816(float* c, const uint32_t* a, uint32_t b0, uint32_t b1) {
    asm volatile(
        "mma.sync.aligned.m16n8k16.row.col.f32.f16.f16.f32 "
        "{%0,%1,%2,%3}, {%4,%5,%6,%7}, {%8,%9}, {%0,%1,%2,%3};"
        : "+f"(c[0]), "+f"(c[1]), "+f"(c[2]), "+f"(c[3])
        : "r"(a[0]), "r"(a[1]), "r"(a[2]), "r"(a[3]), "r"(b0), "r"(b1));
}
__device__ __forceinline__ void cpa16(uint32_t dst, const void* src, int sz) {
    asm volatile("cp.async.cg.shared.global [%0], [%1], 16, %2;"
                 :: "r"(dst), "l"(src), "r"(sz) : "memory");
}
#define CPA_COMMIT() asm volatile("cp.async.commit_group;" ::: "memory")
#define CPA_WAIT0()  asm volatile("cp.async.wait_group 0;" ::: "memory")

__device__ __forceinline__ void store_h4(__half* d, float4 v) {
    __half2 h0 = __floats2half2_rn(v.x, v.y);
    __half2 h1 = __floats2half2_rn(v.z, v.w);
    uint2 u;
    u.x = *(uint32_t*)&h0;
    u.y = *(uint32_t*)&h1;
    *(uint2*)d = u;
}
__device__ __forceinline__ void store_h2(__half* d, float a, float b) {
    __half2 hh = __floats2half2_rn(a, b);
    *(uint32_t*)d = *(uint32_t*)&hh;
}
__device__ __forceinline__ float sigf(float x) { return 1.0f / (1.0f + expf(-x)); }

// SMEM tile geometry: 128 rows x 32 fp16, padded row stride 80B (conflict-free ldmatrix)
#define TROW 80
#define TBYTES (128 * TROW)        // 10240
#define STAGE (2 * TBYTES)         // A, B
#define GSMEM (2 * STAGE)          // 40960

// precomputed per-thread tile-load state (addresses hoisted out of the chunk loop)
struct Pre {
    uint32_t sm0, sm1;       // smem offsets within a tile
    size_t a0, a1;           // A-side global element offsets (row*128 + q*8)
    int az0, az1;            // A-side cp sizes (16 or 0 for OOB rows)
    size_t b0, b1;           // B-side global element offsets (row*strideB + q*8)
};

__device__ __forceinline__ Pre make_pre(int t, int row0, int col0, int strideB) {
    Pre p;
    int q = t & 3;
    int r0 = t >> 2, r1 = r0 + 64;
    p.sm0 = (uint32_t)(r0 * TROW + q * 16);
    p.sm1 = (uint32_t)(r1 * TROW + q * 16);
    int gr0 = row0 + r0, gr1 = row0 + r1;
    p.az0 = gr0 < NN ? 16 : 0;
    p.az1 = gr1 < NN ? 16 : 0;
    if (gr0 >= NN) gr0 = 0;
    if (gr1 >= NN) gr1 = 0;
    p.a0 = (size_t)gr0 * 128 + q * 8;
    p.a1 = (size_t)gr1 * 128 + q * 8;
    p.b0 = (size_t)(col0 + r0) * strideB + q * 8;
    p.b1 = (size_t)(col0 + r1) * strideB + q * 8;
    return p;
}

__device__ __forceinline__ void load_stage(uint32_t buf,
                                           const __half* __restrict__ a,
                                           const __half* __restrict__ b,
                                           int colA, int colB, const Pre& p) {
    cpa16(buf + p.sm0,          a + p.a0 + colA, p.az0);
    cpa16(buf + p.sm1,          a + p.a1 + colA, p.az1);
    cpa16(buf + TBYTES + p.sm0, b + p.b0 + colB, 16);
    cpa16(buf + TBYTES + p.sm1, b + p.b1 + colB, 16);
}

// ---------------- CSR: fused count+scan ----------------
__global__ void __launch_bounds__(1024)
k_countscan(const int* __restrict__ dst) {
    __shared__ int hist[1024];
    __shared__ int ws[32];
    __shared__ int sbase;
    int b = blockIdx.x, t = threadIdx.x;
    int lane = t & 31, wid = t >> 5;
    hist[t] = 0;
    __syncthreads();

    int lo = b << 10;
    int pre = 0;
    const int4* d4 = (const int4*)dst;
    for (int e = t; e < EE / 4; e += 1024) {
        int4 v = __ldg(d4 + e);
        pre += (v.x < lo) + (v.y < lo) + (v.z < lo) + (v.w < lo);
        int dx;
        dx = v.x - lo; if ((unsigned)dx < 1024u) atomicAdd(&hist[dx], 1);
        dx = v.y - lo; if ((unsigned)dx < 1024u) atomicAdd(&hist[dx], 1);
        dx = v.z - lo; if ((unsigned)dx < 1024u) atomicAdd(&hist[dx], 1);
        dx = v.w - lo; if ((unsigned)dx < 1024u) atomicAdd(&hist[dx], 1);
    }
#pragma unroll
    for (int o = 16; o > 0; o >>= 1) pre += __shfl_down_sync(0xffffffffu, pre, o);
    if (lane == 0) ws[wid] = pre;
    __syncthreads();
    if (t < 32) {
        int s = ws[t];
#pragma unroll
        for (int o = 16; o > 0; o >>= 1) s += __shfl_down_sync(0xffffffffu, s, o);
        if (t == 0) sbase = s;
    }
    __syncthreads();
    int base = sbase;
    int v = hist[t];
    __syncthreads();

    int x = v;
#pragma unroll
    for (int o = 1; o < 32; o <<= 1) {
        int y = __shfl_up_sync(0xffffffffu, x, o);
        if (lane >= o) x += y;
    }
    if (lane == 31) ws[wid] = x;
    __syncthreads();
    if (wid == 0) {
        int s = ws[lane];
        int xs = s;
#pragma unroll
        for (int o = 1; o < 32; o <<= 1) {
            int y = __shfl_up_sync(0xffffffffu, xs, o);
            if (lane >= o) xs += y;
        }
        ws[lane] = xs - s;
    }
    __syncthreads();
    int incl = x + ws[wid];
    int i = lo + t;
    if (i < NN) {
        g_rowptr[i] = base + incl - v;
        g_invdeg[i] = 1.0f / fmaxf((float)v, 1.0f);
    }
    if (b == 0 && t == 0) g_rowptr[NN] = EE;
}

// ---------------- fused prep: CSR fill + x fp16 conv + weight packing ----------------
__global__ void k_prep(const int* __restrict__ src, const int* __restrict__ dst,
                       const float* __restrict__ x,
                       const float* __restrict__ Wl, const float* __restrict__ Wr,
                       const float* __restrict__ b) {
    const int W1TN = LL * 384 * 512;
    const int W2TN = LL * 128 * 256;
    int i = blockIdx.x * blockDim.x + threadIdx.x;
    if (i < EE) {
        int d = dst[i];
        int p = atomicAdd(&g_cursor[d], 1);
        g_esrc[g_rowptr[d] + p] = src[i];
    } else if (i < EE + CONVN) {
        int j = i - EE;
        float4 v = __ldg((const float4*)x + j);
        store_h4(g_inp + (size_t)j * 4, v);
    } else {
        int j = i - EE - CONVN;
        if (j < W1TN) {
            int l = j / (384 * 512);
            int rem = j % (384 * 512);
            int c = rem / 512, k = rem % 512;
            int cb = c >> 7, cc = c & 127;
            int s = k >> 7, kk = k & 127;
            float v = 0.0f;
            if (!(cb == 2 && s >= 2)) {
                int g = cb * 2 + (s >> 1);
                const float* W = (s & 1) ? Wr : Wl;
                v = W[(((size_t)l * 6 + g) * 128 + kk) * 128 + cc];
            }
            g_W1T[j] = __float2half_rn(v);
        } else if (j < W1TN + W2TN) {
            int j2 = j - W1TN;
            int l = j2 / (128 * 256);
            int rem = j2 % (128 * 256);
            int c = rem / 256, k = rem % 256;
            int s = k >> 7, kk = k & 127;
            const float* W = s ? Wr : Wl;
            float v = W[(((size_t)l * 6 + 5) * 128 + kk) * 128 + c];
            g_W2T[j2] = __float2half_rn(v);
        } else if (j < W1TN + W2TN + LL * 384) {
            int j2 = j - W1TN - W2TN;
            int l = j2 / 384;
            int c = j2 % 384;
            int cb = c >> 7, cc = c & 127;
            g_bias[j2] = b[(((size_t)l * 6 + cb * 2) * 128) + cc] +
                         b[(((size_t)l * 6 + cb * 2 + 1) * 128) + cc];
        }
    }
}

__global__ void k_zero_end() {
    int i = blockIdx.x * blockDim.x + threadIdx.x;
    if (i < NN) g_cursor[i] = 0;
}

// ---------------- aggregation (warp per dst node, atomic-free via CSR) ----------------
__global__ void k_agg2(const float* __restrict__ A, const float* __restrict__ B) {
    int warp = (blockIdx.x * blockDim.x + threadIdx.x) >> 5;
    int lane = threadIdx.x & 31;
    if (warp >= NN) return;
    int e = g_rowptr[warp], end = g_rowptr[warp + 1];
    float4 aa = make_float4(0.f, 0.f, 0.f, 0.f);
    float4 ab = make_float4(0.f, 0.f, 0.f, 0.f);
    for (; e + 3 < end; e += 4) {
        int s0 = g_esrc[e], s1 = g_esrc[e + 1], s2 = g_esrc[e + 2], s3 = g_esrc[e + 3];
        float4 va0 = __ldg((const float4*)(A + (size_t)s0 * DD) + lane);
        float4 va1 = __ldg((const float4*)(A + (size_t)s1 * DD) + lane);
        float4 va2 = __ldg((const float4*)(A + (size_t)s2 * DD) + lane);
        float4 va3 = __ldg((const float4*)(A + (size_t)s3 * DD) + lane);
        float4 vb0 = __ldg((const float4*)(B + (size_t)s0 * DD) + lane);
        float4 vb1 = __ldg((const float4*)(B + (size_t)s1 * DD) + lane);
        float4 vb2 = __ldg((const float4*)(B + (size_t)s2 * DD) + lane);
        float4 vb3 = __ldg((const float4*)(B + (size_t)s3 * DD) + lane);
        aa.x += (va0.x + va1.x) + (va2.x + va3.x);
        aa.y += (va0.y + va1.y) + (va2.y + va3.y);
        aa.z += (va0.z + va1.z) + (va2.z + va3.z);
        aa.w += (va0.w + va1.w) + (va2.w + va3.w);
        ab.x += (vb0.x + vb1.x) + (vb2.x + vb3.x);
        ab.y += (vb0.y + vb1.y) + (vb2.y + vb3.y);
        ab.z += (vb0.z + vb1.z) + (vb2.z + vb3.z);
        ab.w += (vb0.w + vb1.w) + (vb2.w + vb3.w);
    }
    for (; e < end; e++) {
        int s0 = g_esrc[e];
        float4 va0 = __ldg((const float4*)(A + (size_t)s0 * DD) + lane);
        float4 vb0 = __ldg((const float4*)(B + (size_t)s0 * DD) + lane);
        aa.x += va0.x; aa.y += va0.y; aa.z += va0.z; aa.w += va0.w;
        ab.x += vb0.x; ab.y += vb0.y; ab.z += vb0.z; ab.w += vb0.w;
    }
    float sc = g_invdeg[warp];
    aa.x *= sc; aa.y *= sc; aa.z *= sc; aa.w *= sc;
    ab.x *= sc; ab.y *= sc; ab.z *= sc; ab.w *= sc;
    size_t o = (size_t)warp * DD + lane * 4;
    store_h4(g_agga + o, aa);
    store_h4(g_aggb + o, ab);
    // fused: fp16 copy of hl row for GEMM1's h operand segment
    float4 hv = __ldg((const float4*)(B + (size_t)warp * DD) + lane);
    store_h4(g_h + o, hv);
}

// agg of r*h: gathers fp16 (8B/lane/edge)
__global__ void k_agg1() {
    int warp = (blockIdx.x * blockDim.x + threadIdx.x) >> 5;
    int lane = threadIdx.x & 31;
    if (warp >= NN) return;
    int e = g_rowptr[warp], end = g_rowptr[warp + 1];
    float4 aa = make_float4(0.f, 0.f, 0.f, 0.f);
    for (; e + 3 < end; e += 4) {
        int s0 = g_esrc[e], s1 = g_esrc[e + 1], s2 = g_esrc[e + 2], s3 = g_esrc[e + 3];
        uint2 v0 = __ldg((const uint2*)(g_rh + (size_t)s0 * DD) + lane);
        uint2 v1 = __ldg((const uint2*)(g_rh + (size_t)s1 * DD) + lane);
        uint2 v2 = __ldg((const uint2*)(g_rh + (size_t)s2 * DD) + lane);
        uint2 v3 = __ldg((const uint2*)(g_rh + (size_t)s3 * DD) + lane);
        float2 a0 = __half22float2(*(__half2*)&v0.x), a1 = __half22float2(*(__half2*)&v0.y);
        float2 b0 = __half22float2(*(__half2*)&v1.x), b1 = __half22float2(*(__half2*)&v1.y);
        float2 c0 = __half22float2(*(__half2*)&v2.x), c1 = __half22float2(*(__half2*)&v2.y);
        float2 d0 = __half22float2(*(__half2*)&v3.x), d1 = __half22float2(*(__half2*)&v3.y);
        aa.x += (a0.x + b0.x) + (c0.x + d0.x);
        aa.y += (a0.y + b0.y) + (c0.y + d0.y);
        aa.z += (a1.x + b1.x) + (c1.x + d1.x);
        aa.w += (a1.y + b1.y) + (c1.y + d1.y);
    }
    for (; e < end; e++) {
        int s0 = g_esrc[e];
        uint2 v0 = __ldg((const uint2*)(g_rh + (size_t)s0 * DD) + lane);
        float2 a0 = __half22float2(*(__half2*)&v0.x), a1 = __half22float2(*(__half2*)&v0.y);
        aa.x += a0.x; aa.y += a0.y; aa.z += a1.x; aa.w += a1.y;
    }
    float sc = g_invdeg[warp];
    aa.x *= sc; aa.y *= sc; aa.z *= sc; aa.w *= sc;
    size_t o = (size_t)warp * DD + lane * 2 * 2;
    store_h4(g_agga + (size_t)warp * DD + lane * 4, aa);
    (void)o;
}

// ---------------- HMMA GEMM core: single fp16 pass ----------------
__device__ __forceinline__ void gemm_chunk(uint32_t sA, uint32_t lsm_a, uint32_t lsm_b,
                                           float acc[2][8][4]) {
    uint32_t sB = sA + TBYTES;
#pragma unroll
    for (int kb = 0; kb < 2; kb++) {
        uint32_t ko = kb * 32;
        uint32_t aoff = lsm_a + ko;
        uint32_t boff = lsm_b + ko;
        uint32_t Af[2][4], Bf[4][4];
        ldsm4(Af[0], sA + aoff);
        ldsm4(Af[1], sA + aoff + 16 * TROW);
#pragma unroll
        for (int ng = 0; ng < 4; ng++) ldsm4(Bf[ng], sB + boff + ng * 16 * TROW);
#pragma unroll
        for (int mt = 0; mt < 2; mt++)
#pragma unroll
            for (int nt = 0; nt < 8; nt++) {
                int ng = nt >> 1, o = nt & 1;
                mma16816(acc[mt][nt], Af[mt], Bf[ng][o], Bf[ng][o + 2]);
            }
    }
}

// ---------------- GEMM1: [N,512]x[512,384] fused z / r*h / hx ----------------
// cb==2 (hx) uses only K-segments {agg_inp, inp}: 8 chunks instead of 16.
__global__ void __launch_bounds__(256, 2)
k_gemm1(const float* __restrict__ hl, int l) {
    extern __shared__ __align__(16) char smdyn[];
    uint32_t sb = smem_u32(smdyn);
    int t = threadIdx.x;
    int row0 = blockIdx.y * 128;
    int cb = blockIdx.x;
    int col0 = cb * 128;
    const int NC = (cb == 2) ? 8 : 16;

    const __half* __restrict__ W = g_W1T + (size_t)l * 384 * 512;
    const __half* segs[4] = { g_agga, g_inp, g_aggb, g_h };

    const Pre p = make_pre(t, row0, col0, 512);
    int lane = t & 31, wid = t >> 5;
    int wm = wid & 3, wn = wid >> 2;
    uint32_t rsel = (uint32_t)(lane & 15) * TROW + (uint32_t)(lane >> 4) * 16;
    uint32_t lsm_a = (uint32_t)(wm * 32) * TROW + rsel;
    uint32_t lsm_b = (uint32_t)(wn * 64) * TROW + rsel;

    float acc[2][8][4];
#pragma unroll
    for (int i = 0; i < 2; i++)
#pragma unroll
        for (int j = 0; j < 8; j++)
#pragma unroll
            for (int q = 0; q < 4; q++) acc[i][j][q] = 0.0f;

    load_stage(sb, segs[0], W, 0, 0, p);
    CPA_COMMIT();
    for (int c = 0; c < NC; c++) {
        CPA_WAIT0();
        __syncthreads();
        if (c + 1 < NC) {
            int cn = c + 1;
            int seg = cn >> 2, colA = (cn & 3) * 32, colB = cn * 32;
            load_stage(sb + (cn & 1) * STAGE, segs[seg], W, colA, colB, p);
            CPA_COMMIT();
        }
        gemm_chunk(sb + (c & 1) * STAGE, lsm_a, lsm_b, acc);
    }

    // epilogue
    const float* bias = g_bias + l * 384;
#pragma unroll
    for (int mt = 0; mt < 2; mt++)
#pragma unroll
        for (int nt = 0; nt < 8; nt++) {
            int row = row0 + wm * 32 + mt * 16 + (lane >> 2);
            int col = col0 + wn * 64 + nt * 8 + (lane & 3) * 2;
            float b0 = __ldg(bias + col), b1 = __ldg(bias + col + 1);
            int ccol = col & 127;
#pragma unroll
            for (int half = 0; half < 2; half++) {
                int r = row + half * 8;
                if (r >= NN) continue;
                float v0 = acc[mt][nt][half * 2 + 0] + b0;
                float v1 = acc[mt][nt][half * 2 + 1] + b1;
                size_t idx = (size_t)r * 128 + ccol;
                if (cb == 0) {
                    float2 z = make_float2(sigf(v0), sigf(v1));
                    *(float2*)(g_Z + idx) = z;
                } else if (cb == 1) {
                    float h0 = hl[idx], h1 = hl[idx + 1];
                    float rh0 = sigf(v0) * h0, rh1 = sigf(v1) * h1;
                    store_h2(g_rh + idx, rh0, rh1);
                } else {
                    *(float2*)(g_HX + idx) = make_float2(v0, v1);
                }
            }
        }
}

// ---------------- GEMM2: [N,256]x[256,128] fused GRU mix ----------------
__global__ void __launch_bounds__(256, 2)
k_gemm2(const float* __restrict__ hl, float* __restrict__ out, int l) {
    extern __shared__ __align__(16) char smdyn[];
    uint32_t sb = smem_u32(smdyn);
    int t = threadIdx.x;
    int row0 = blockIdx.y * 128;

    const __half* __restrict__ W = g_W2T + (size_t)l * 128 * 256;
    const __half* segs[2] = { g_agga, g_rh };

    const Pre p = make_pre(t, row0, 0, 256);
    int lane = t & 31, wid = t >> 5;
    int wm = wid & 3, wn = wid >> 2;
    uint32_t rsel = (uint32_t)(lane & 15) * TROW + (uint32_t)(lane >> 4) * 16;
    uint32_t lsm_a = (uint32_t)(wm * 32) * TROW + rsel;
    uint32_t lsm_b = (uint32_t)(wn * 64) * TROW + rsel;

    float acc[2][8][4];
#pragma unroll
    for (int i = 0; i < 2; i++)
#pragma unroll
        for (int j = 0; j < 8; j++)
#pragma unroll
            for (int q = 0; q < 4; q++) acc[i][j][q] = 0.0f;

    load_stage(sb, segs[0], W, 0, 0, p);
    CPA_COMMIT();
    for (int c = 0; c < 8; c++) {
        CPA_WAIT0();
        __syncthreads();
        if (c + 1 < 8) {
            int cn = c + 1;
            int seg = cn >> 2, colA = (cn & 3) * 32, colB = cn * 32;
            load_stage(sb + (cn & 1) * STAGE, segs[seg], W, colA, colB, p);
            CPA_COMMIT();
        }
        gemm_chunk(sb + (c & 1) * STAGE, lsm_a, lsm_b, acc);
    }

#pragma unroll
    for (int mt = 0; mt < 2; mt++)
#pragma unroll
        for (int nt = 0; nt < 8; nt++) {
            int row = row0 + wm * 32 + mt * 16 + (lane >> 2);
            int col = wn * 64 + nt * 8 + (lane & 3) * 2;
#pragma unroll
            for (int half = 0; half < 2; half++) {
                int r = row + half * 8;
                if (r >= NN) continue;
                size_t idx = (size_t)r * 128 + col;
                float hx0 = g_HX[idx], hx1 = g_HX[idx + 1];
                float z0 = g_Z[idx], z1 = g_Z[idx + 1];
                float h0 = hl[idx], h1 = hl[idx + 1];
                float ht0 = tanhf(acc[mt][nt][half * 2 + 0] + hx0);
                float ht1 = tanhf(acc[mt][nt][half * 2 + 1] + hx1);
                float o0 = z0 * h0 + (1.0f - z0) * ht0;
                float o1 = z1 * h1 + (1.0f - z1) * ht1;
                *(float2*)(out + idx) = make_float2(o0, o1);
                store_h2(g_inp + idx, o0, o1);
            }
        }
}

// ---------------- launch ----------------
extern "C" void kernel_launch(void* const* d_in, const int* in_sizes, int n_in,
                              void* d_out, int out_size) {
    const float* x  = (const float*)d_in[0];
    const float* h  = (const float*)d_in[1];
    const float* Wl = (const float*)d_in[2];
    const float* Wr = (const float*)d_in[3];
    const float* b  = (const float*)d_in[4];
    const int* src  = (const int*)d_in[5];
    const int* dst  = (const int*)d_in[6];
    float* out = (float*)d_out;

    cudaFuncSetAttribute(k_gemm1, cudaFuncAttributeMaxDynamicSharedMemorySize, GSMEM);
    cudaFuncSetAttribute(k_gemm2, cudaFuncAttributeMaxDynamicSharedMemorySize, GSMEM);

    const int ROWT = (NN + 127) / 128;
    const int WTOT = LL * 384 * 512 + LL * 128 * 256 + LL * 384;
    const int PREPN = EE + CONVN + WTOT;

    k_countscan<<<NCHUNK, 1024>>>(dst);
    k_prep<<<(PREPN + 255) / 256, 256>>>(src, dst, x, Wl, Wr, b);

    for (int l = 0; l < LL; l++) {
        const float* hl = h + (size_t)l * NN * DD;
        k_agg2<<<(NN * 32 + 255) / 256, 256>>>(
            (l == 0) ? x : (out + (size_t)(l - 1) * NN * DD), hl);
        dim3 g1(3, ROWT);
        k_gemm1<<<g1, 256, GSMEM>>>(hl, l);   // launch #4 <- ncu target
        k_agg1<<<(NN * 32 + 255) / 256, 256>>>();
        dim3 g2(1, ROWT);
        k_gemm2<<<g2, 256, GSMEM>>>(hl, out + (size_t)l * NN * DD, l);
    }

    k_zero_end<<<(NN + 255) / 256, 256>>>();
}

// round 12
// speedup vs baseline: 1.5988x; 1.0491x over previous
#include <cuda_runtime.h>
#include <cuda_fp16.h>
#include <math.h>
#include <stdint.h>

// Problem constants (fixed by setup_inputs)
#define NN 50000
#define EE 800000
#define DD 128
#define LL 2
#define NCHUNK ((NN + 1023) / 1024)
#define CONVN (NN * DD / 4)

// ---------------- scratch (static __device__ globals; no allocation) ----------------
// g_cursor is zeroed by k_zero_end at the END of each launch (module-load zero-init
// covers the first call).
__device__ float g_bias[LL * 384];
__device__ float g_invdeg[NN];
__device__ int g_rowptr[NN + 1];
__device__ int g_cursor[NN];
__device__ int g_esrc[EE];

// fp16 operands (single-pass HMMA; error model validated R11)
__device__ __align__(16) __half g_Z[NN * DD];
__device__ __align__(16) __half g_HX[NN * DD];
__device__ __align__(16) __half g_inp[NN * DD];
__device__ __align__(16) __half g_h[LL * NN * DD];   // both layers, converted in prep
__device__ __align__(16) __half g_agga[NN * DD];
__device__ __align__(16) __half g_aggb[NN * DD];
__device__ __align__(16) __half g_rh[NN * DD];
__device__ __align__(16) __half g_W1T[LL * 384 * 512];
__device__ __align__(16) __half g_W2T[LL * 128 * 256];

// ---------------- helpers ----------------
__device__ __forceinline__ uint32_t smem_u32(const void* p) {
    uint32_t a;
    asm("{ .reg .u64 t; cvta.to.shared.u64 t, %1; cvt.u32.u64 %0, t; }" : "=r"(a) : "l"(p));
    return a;
}
__device__ __forceinline__ void ldsm4(uint32_t* f, uint32_t addr) {
    asm volatile("ldmatrix.sync.aligned.m8n8.x4.shared.b16 {%0,%1,%2,%3}, [%4];"
                 : "=r"(f[0]), "=r"(f[1]), "=r"(f[2]), "=r"(f[3]) : "r"(addr));
}
__device__ __forceinline__ void mma16816(float* c, const uint32_t* a, uint32_t b0, uint32_t b1) {
    asm volatile(
        "mma.sync.aligned.m16n8k16.row.col.f32.f16.f16.f32 "
        "{%0,%1,%2,%3}, {%4,%5,%6,%7}, {%8,%9}, {%0,%1,%2,%3};"
        : "+f"(c[0]), "+f"(c[1]), "+f"(c[2]), "+f"(c[3])
        : "r"(a[0]), "r"(a[1]), "r"(a[2]), "r"(a[3]), "r"(b0), "r"(b1));
}
__device__ __forceinline__ void cpa16(uint32_t dst, const void* src, int sz) {
    asm volatile("cp.async.cg.shared.global [%0], [%1], 16, %2;"
                 :: "r"(dst), "l"(src), "r"(sz) : "memory");
}
#define CPA_COMMIT() asm volatile("cp.async.commit_group;" ::: "memory")
#define CPA_WAIT0()  asm volatile("cp.async.wait_group 0;" ::: "memory")

__device__ __forceinline__ void store_h4(__half* d, float4 v) {
    __half2 h0 = __floats2half2_rn(v.x, v.y);
    __half2 h1 = __floats2half2_rn(v.z, v.w);
    uint2 u;
    u.x = *(uint32_t*)&h0;
    u.y = *(uint32_t*)&h1;
    *(uint2*)d = u;
}
__device__ __forceinline__ void store_h2(__half* d, float a, float b) {
    __half2 hh = __floats2half2_rn(a, b);
    *(uint32_t*)d = *(uint32_t*)&hh;
}
__device__ __forceinline__ float sigf(float x) { return 1.0f / (1.0f + expf(-x)); }

// SMEM tile geometry: 128 rows x 32 fp16 subtile, padded row stride 80B
#define TROW 80
#define TBYTES (128 * TROW)        // 10240
#define STAGE (4 * TBYTES)         // {A0,B0,A1,B1} = K64 chunk, 40KB
#define GSMEM (2 * STAGE)          // 81920

// precomputed per-thread tile-load state
struct Pre {
    uint32_t sm0, sm1;
    size_t a0, a1;
    int az0, az1;
    size_t b0, b1;
};

__device__ __forceinline__ Pre make_pre(int t, int row0, int col0, int strideB) {
    Pre p;
    int q = t & 3;
    int r0 = t >> 2, r1 = r0 + 64;
    p.sm0 = (uint32_t)(r0 * TROW + q * 16);
    p.sm1 = (uint32_t)(r1 * TROW + q * 16);
    int gr0 = row0 + r0, gr1 = row0 + r1;
    p.az0 = gr0 < NN ? 16 : 0;
    p.az1 = gr1 < NN ? 16 : 0;
    if (gr0 >= NN) gr0 = 0;
    if (gr1 >= NN) gr1 = 0;
    p.a0 = (size_t)gr0 * 128 + q * 8;
    p.a1 = (size_t)gr1 * 128 + q * 8;
    p.b0 = (size_t)(col0 + r0) * strideB + q * 8;
    p.b1 = (size_t)(col0 + r1) * strideB + q * 8;
    return p;
}

// one 32-col {A,B} subtile pair
__device__ __forceinline__ void load_sub(uint32_t buf,
                                         const __half* __restrict__ a,
                                         const __half* __restrict__ b,
                                         int colA, int colB, const Pre& p) {
    cpa16(buf + p.sm0,          a + p.a0 + colA, p.az0);
    cpa16(buf + p.sm1,          a + p.a1 + colA, p.az1);
    cpa16(buf + TBYTES + p.sm0, b + p.b0 + colB, 16);
    cpa16(buf + TBYTES + p.sm1, b + p.b1 + colB, 16);
}
// K64 stage = two subtile pairs
__device__ __forceinline__ void load_stage64(uint32_t buf,
                                             const __half* __restrict__ a,
                                             const __half* __restrict__ b,
                                             int colA, int colB, const Pre& p) {
    load_sub(buf,              a, b, colA,      colB,      p);
    load_sub(buf + 2 * TBYTES, a, b, colA + 32, colB + 32, p);
}

// ---------------- CSR: fused count+scan ----------------
__global__ void __launch_bounds__(1024)
k_countscan(const int* __restrict__ dst) {
    __shared__ int hist[1024];
    __shared__ int ws[32];
    __shared__ int sbase;
    int b = blockIdx.x, t = threadIdx.x;
    int lane = t & 31, wid = t >> 5;
    hist[t] = 0;
    __syncthreads();

    int lo = b << 10;
    int pre = 0;
    const int4* d4 = (const int4*)dst;
    for (int e = t; e < EE / 4; e += 1024) {
        int4 v = __ldg(d4 + e);
        pre += (v.x < lo) + (v.y < lo) + (v.z < lo) + (v.w < lo);
        int dx;
        dx = v.x - lo; if ((unsigned)dx < 1024u) atomicAdd(&hist[dx], 1);
        dx = v.y - lo; if ((unsigned)dx < 1024u) atomicAdd(&hist[dx], 1);
        dx = v.z - lo; if ((unsigned)dx < 1024u) atomicAdd(&hist[dx], 1);
        dx = v.w - lo; if ((unsigned)dx < 1024u) atomicAdd(&hist[dx], 1);
    }
#pragma unroll
    for (int o = 16; o > 0; o >>= 1) pre += __shfl_down_sync(0xffffffffu, pre, o);
    if (lane == 0) ws[wid] = pre;
    __syncthreads();
    if (t < 32) {
        int s = ws[t];
#pragma unroll
        for (int o = 16; o > 0; o >>= 1) s += __shfl_down_sync(0xffffffffu, s, o);
        if (t == 0) sbase = s;
    }
    __syncthreads();
    int base = sbase;
    int v = hist[t];
    __syncthreads();

    int x = v;
#pragma unroll
    for (int o = 1; o < 32; o <<= 1) {
        int y = __shfl_up_sync(0xffffffffu, x, o);
        if (lane >= o) x += y;
    }
    if (lane == 31) ws[wid] = x;
    __syncthreads();
    if (wid == 0) {
        int s = ws[lane];
        int xs = s;
#pragma unroll
        for (int o = 1; o < 32; o <<= 1) {
            int y = __shfl_up_sync(0xffffffffu, xs, o);
            if (lane >= o) xs += y;
        }
        ws[lane] = xs - s;
    }
    __syncthreads();
    int incl = x + ws[wid];
    int i = lo + t;
    if (i < NN) {
        g_rowptr[i] = base + incl - v;
        g_invdeg[i] = 1.0f / fmaxf((float)v, 1.0f);
    }
    if (b == 0 && t == 0) g_rowptr[NN] = EE;
}

// ---------------- fused prep: CSR fill + x & h fp16 conv + weight packing ----------------
__global__ void k_prep(const int* __restrict__ src, const int* __restrict__ dst,
                       const float* __restrict__ x, const float* __restrict__ h,
                       const float* __restrict__ Wl, const float* __restrict__ Wr,
                       const float* __restrict__ b) {
    const int W1TN = LL * 384 * 512;
    const int W2TN = LL * 128 * 256;
    int i = blockIdx.x * blockDim.x + threadIdx.x;
    if (i < EE) {
        int d = dst[i];
        int p = atomicAdd(&g_cursor[d], 1);
        g_esrc[g_rowptr[d] + p] = src[i];
    } else if (i < EE + CONVN) {
        int j = i - EE;
        float4 v = __ldg((const float4*)x + j);
        store_h4(g_inp + (size_t)j * 4, v);
    } else if (i < EE + CONVN + LL * CONVN) {
        int j = i - EE - CONVN;
        float4 v = __ldg((const float4*)h + j);
        store_h4(g_h + (size_t)j * 4, v);
    } else {
        int j = i - EE - CONVN - LL * CONVN;
        if (j < W1TN) {
            int l = j / (384 * 512);
            int rem = j % (384 * 512);
            int c = rem / 512, k = rem % 512;
            int cb = c >> 7, cc = c & 127;
            int s = k >> 7, kk = k & 127;
            float v = 0.0f;
            if (!(cb == 2 && s >= 2)) {
                int g = cb * 2 + (s >> 1);
                const float* W = (s & 1) ? Wr : Wl;
                v = W[(((size_t)l * 6 + g) * 128 + kk) * 128 + cc];
            }
            g_W1T[j] = __float2half_rn(v);
        } else if (j < W1TN + W2TN) {
            int j2 = j - W1TN;
            int l = j2 / (128 * 256);
            int rem = j2 % (128 * 256);
            int c = rem / 256, k = rem % 256;
            int s = k >> 7, kk = k & 127;
            const float* W = s ? Wr : Wl;
            float v = W[(((size_t)l * 6 + 5) * 128 + kk) * 128 + c];
            g_W2T[j2] = __float2half_rn(v);
        } else if (j < W1TN + W2TN + LL * 384) {
            int j2 = j - W1TN - W2TN;
            int l = j2 / 384;
            int c = j2 % 384;
            int cb = c >> 7, cc = c & 127;
            g_bias[j2] = b[(((size_t)l * 6 + cb * 2) * 128) + cc] +
                         b[(((size_t)l * 6 + cb * 2 + 1) * 128) + cc];
        }
    }
}

__global__ void k_zero_end() {
    int i = blockIdx.x * blockDim.x + threadIdx.x;
    if (i < NN) g_cursor[i] = 0;
}

// ---------------- aggregation: gathers fp16 rows (256B/row), fp32 accumulate ----------------
__global__ void k_agg2(int l) {
    int warp = (blockIdx.x * blockDim.x + threadIdx.x) >> 5;
    int lane = threadIdx.x & 31;
    if (warp >= NN) return;
    const __half* __restrict__ A = g_inp;
    const __half* __restrict__ B = g_h + (size_t)l * NN * DD;
    int e = g_rowptr[warp], end = g_rowptr[warp + 1];
    float4 aa = make_float4(0.f, 0.f, 0.f, 0.f);
    float4 ab = make_float4(0.f, 0.f, 0.f, 0.f);
    for (; e + 3 < end; e += 4) {
        int s0 = g_esrc[e], s1 = g_esrc[e + 1], s2 = g_esrc[e + 2], s3 = g_esrc[e + 3];
        uint2 va0 = __ldg((const uint2*)(A + (size_t)s0 * DD) + lane);
        uint2 va1 = __ldg((const uint2*)(A + (size_t)s1 * DD) + lane);
        uint2 va2 = __ldg((const uint2*)(A + (size_t)s2 * DD) + lane);
        uint2 va3 = __ldg((const uint2*)(A + (size_t)s3 * DD) + lane);
        uint2 vb0 = __ldg((const uint2*)(B + (size_t)s0 * DD) + lane);
        uint2 vb1 = __ldg((const uint2*)(B + (size_t)s1 * DD) + lane);
        uint2 vb2 = __ldg((const uint2*)(B + (size_t)s2 * DD) + lane);
        uint2 vb3 = __ldg((const uint2*)(B + (size_t)s3 * DD) + lane);
#define ACC4(dst, v) do { \
        float2 _p0 = __half22float2(*(__half2*)&(v).x); \
        float2 _p1 = __half22float2(*(__half2*)&(v).y); \
        dst.x += _p0.x; dst.y += _p0.y; dst.z += _p1.x; dst.w += _p1.y; } while (0)
        ACC4(aa, va0); ACC4(aa, va1); ACC4(aa, va2); ACC4(aa, va3);
        ACC4(ab, vb0); ACC4(ab, vb1); ACC4(ab, vb2); ACC4(ab, vb3);
    }
    for (; e < end; e++) {
        int s0 = g_esrc[e];
        uint2 va0 = __ldg((const uint2*)(A + (size_t)s0 * DD) + lane);
        uint2 vb0 = __ldg((const uint2*)(B + (size_t)s0 * DD) + lane);
        ACC4(aa, va0); ACC4(ab, vb0);
    }
    float sc = g_invdeg[warp];
    aa.x *= sc; aa.y *= sc; aa.z *= sc; aa.w *= sc;
    ab.x *= sc; ab.y *= sc; ab.z *= sc; ab.w *= sc;
    size_t o = (size_t)warp * DD + lane * 4;
    store_h4(g_agga + o, aa);
    store_h4(g_aggb + o, ab);
}

__global__ void k_agg1() {
    int warp = (blockIdx.x * blockDim.x + threadIdx.x) >> 5;
    int lane = threadIdx.x & 31;
    if (warp >= NN) return;
    int e = g_rowptr[warp], end = g_rowptr[warp + 1];
    float4 aa = make_float4(0.f, 0.f, 0.f, 0.f);
    for (; e + 3 < end; e += 4) {
        int s0 = g_esrc[e], s1 = g_esrc[e + 1], s2 = g_esrc[e + 2], s3 = g_esrc[e + 3];
        uint2 v0 = __ldg((const uint2*)(g_rh + (size_t)s0 * DD) + lane);
        uint2 v1 = __ldg((const uint2*)(g_rh + (size_t)s1 * DD) + lane);
        uint2 v2 = __ldg((const uint2*)(g_rh + (size_t)s2 * DD) + lane);
        uint2 v3 = __ldg((const uint2*)(g_rh + (size_t)s3 * DD) + lane);
        ACC4(aa, v0); ACC4(aa, v1); ACC4(aa, v2); ACC4(aa, v3);
    }
    for (; e < end; e++) {
        int s0 = g_esrc[e];
        uint2 v0 = __ldg((const uint2*)(g_rh + (size_t)s0 * DD) + lane);
        ACC4(aa, v0);
    }
    float sc = g_invdeg[warp];
    aa.x *= sc; aa.y *= sc; aa.z *= sc; aa.w *= sc;
    store_h4(g_agga + (size_t)warp * DD + lane * 4, aa);
}
#undef ACC4

// ---------------- HMMA core: one 32-col subtile pair ----------------
__device__ __forceinline__ void gemm_sub(uint32_t sA, uint32_t lsm_a, uint32_t lsm_b,
                                         float acc[2][8][4]) {
    uint32_t sB = sA + TBYTES;
#pragma unroll
    for (int kb = 0; kb < 2; kb++) {
        uint32_t ko = kb * 32;
        uint32_t aoff = lsm_a + ko;
        uint32_t boff = lsm_b + ko;
        uint32_t Af[2][4], Bf[4][4];
        ldsm4(Af[0], sA + aoff);
        ldsm4(Af[1], sA + aoff + 16 * TROW);
#pragma unroll
        for (int ng = 0; ng < 4; ng++) ldsm4(Bf[ng], sB + boff + ng * 16 * TROW);
#pragma unroll
        for (int mt = 0; mt < 2; mt++)
#pragma unroll
            for (int nt = 0; nt < 8; nt++) {
                int ng = nt >> 1, o = nt & 1;
                mma16816(acc[mt][nt], Af[mt], Bf[ng][o], Bf[ng][o + 2]);
            }
    }
}

// ---------------- GEMM1: [N,512]x[512,384] fused z / r*h / hx, K64 chunks ----------------
// cb==2 (hx) uses only K-segments {agg_inp, inp}: 4 chunks instead of 8.
__global__ void __launch_bounds__(256, 2)
k_gemm1(const float* __restrict__ hl, int l) {
    extern __shared__ __align__(16) char smdyn[];
    uint32_t sb = smem_u32(smdyn);
    int t = threadIdx.x;
    int row0 = blockIdx.y * 128;
    int cb = blockIdx.x;
    int col0 = cb * 128;
    const int NC = (cb == 2) ? 4 : 8;   // K64 chunks

    const __half* __restrict__ W = g_W1T + (size_t)l * 384 * 512;
    const __half* segs[4] = { g_agga, g_inp, g_aggb, g_h + (size_t)l * NN * DD };

    const Pre p = make_pre(t, row0, col0, 512);
    int lane = t & 31, wid = t >> 5;
    int wm = wid & 3, wn = wid >> 2;
    uint32_t rsel = (uint32_t)(lane & 15) * TROW + (uint32_t)(lane >> 4) * 16;
    uint32_t lsm_a = (uint32_t)(wm * 32) * TROW + rsel;
    uint32_t lsm_b = (uint32_t)(wn * 64) * TROW + rsel;

    float acc[2][8][4];
#pragma unroll
    for (int i = 0; i < 2; i++)
#pragma unroll
        for (int j = 0; j < 8; j++)
#pragma unroll
            for (int q = 0; q < 4; q++) acc[i][j][q] = 0.0f;

    load_stage64(sb, segs[0], W, 0, 0, p);
    CPA_COMMIT();
    for (int c = 0; c < NC; c++) {
        CPA_WAIT0();
        __syncthreads();
        if (c + 1 < NC) {
            int cn = c + 1;
            int seg = cn >> 1, colA = (cn & 1) * 64, colB = cn * 64;
            load_stage64(sb + (cn & 1) * STAGE, segs[seg], W, colA, colB, p);
            CPA_COMMIT();
        }
        uint32_t buf = sb + (c & 1) * STAGE;
        gemm_sub(buf, lsm_a, lsm_b, acc);
        gemm_sub(buf + 2 * TBYTES, lsm_a, lsm_b, acc);
    }

    // epilogue
    const float* bias = g_bias + l * 384;
#pragma unroll
    for (int mt = 0; mt < 2; mt++)
#pragma unroll
        for (int nt = 0; nt < 8; nt++) {
            int row = row0 + wm * 32 + mt * 16 + (lane >> 2);
            int col = col0 + wn * 64 + nt * 8 + (lane & 3) * 2;
            float b0 = __ldg(bias + col), b1 = __ldg(bias + col + 1);
            int ccol = col & 127;
#pragma unroll
            for (int half = 0; half < 2; half++) {
                int r = row + half * 8;
                if (r >= NN) continue;
                float v0 = acc[mt][nt][half * 2 + 0] + b0;
                float v1 = acc[mt][nt][half * 2 + 1] + b1;
                size_t idx = (size_t)r * 128 + ccol;
                if (cb == 0) {
                    store_h2(g_Z + idx, sigf(v0), sigf(v1));
                } else if (cb == 1) {
                    float h0 = hl[idx], h1 = hl[idx + 1];
                    store_h2(g_rh + idx, sigf(v0) * h0, sigf(v1) * h1);
                } else {
                    store_h2(g_HX + idx, v0, v1);
                }
            }
        }
}

// ---------------- GEMM2: [N,256]x[256,128] fused GRU mix, K64 chunks ----------------
__global__ void __launch_bounds__(256, 2)
k_gemm2(const float* __restrict__ hl, float* __restrict__ out, int l) {
    extern __shared__ __align__(16) char smdyn[];
    uint32_t sb = smem_u32(smdyn);
    int t = threadIdx.x;
    int row0 = blockIdx.y * 128;

    const __half* __restrict__ W = g_W2T + (size_t)l * 128 * 256;
    const __half* segs[2] = { g_agga, g_rh };

    const Pre p = make_pre(t, row0, 0, 256);
    int lane = t & 31, wid = t >> 5;
    int wm = wid & 3, wn = wid >> 2;
    uint32_t rsel = (uint32_t)(lane & 15) * TROW + (uint32_t)(lane >> 4) * 16;
    uint32_t lsm_a = (uint32_t)(wm * 32) * TROW + rsel;
    uint32_t lsm_b = (uint32_t)(wn * 64) * TROW + rsel;

    float acc[2][8][4];
#pragma unroll
    for (int i = 0; i < 2; i++)
#pragma unroll
        for (int j = 0; j < 8; j++)
#pragma unroll
            for (int q = 0; q < 4; q++) acc[i][j][q] = 0.0f;

    load_stage64(sb, segs[0], W, 0, 0, p);
    CPA_COMMIT();
    for (int c = 0; c < 4; c++) {
        CPA_WAIT0();
        __syncthreads();
        if (c + 1 < 4) {
            int cn = c + 1;
            int seg = cn >> 1, colA = (cn & 1) * 64, colB = cn * 64;
            load_stage64(sb + (cn & 1) * STAGE, segs[seg], W, colA, colB, p);
            CPA_COMMIT();
        }
        uint32_t buf = sb + (c & 1) * STAGE;
        gemm_sub(buf, lsm_a, lsm_b, acc);
        gemm_sub(buf + 2 * TBYTES, lsm_a, lsm_b, acc);
    }

#pragma unroll
    for (int mt = 0; mt < 2; mt++)
#pragma unroll
        for (int nt = 0; nt < 8; nt++) {
            int row = row0 + wm * 32 + mt * 16 + (lane >> 2);
            int col = wn * 64 + nt * 8 + (lane & 3) * 2;
#pragma unroll
            for (int half = 0; half < 2; half++) {
                int r = row + half * 8;
                if (r >= NN) continue;
                size_t idx = (size_t)r * 128 + col;
                float2 hx = __half22float2(*(const __half2*)(g_HX + idx));
                float2 zz = __half22float2(*(const __half2*)(g_Z + idx));
                float h0 = hl[idx], h1 = hl[idx + 1];
                float ht0 = tanhf(acc[mt][nt][half * 2 + 0] + hx.x);
                float ht1 = tanhf(acc[mt][nt][half * 2 + 1] + hx.y);
                float o0 = zz.x * h0 + (1.0f - zz.x) * ht0;
                float o1 = zz.y * h1 + (1.0f - zz.y) * ht1;
                *(float2*)(out + idx) = make_float2(o0, o1);
                store_h2(g_inp + idx, o0, o1);
            }
        }
}

// ---------------- launch ----------------
extern "C" void kernel_launch(void* const* d_in, const int* in_sizes, int n_in,
                              void* d_out, int out_size) {
    const float* x  = (const float*)d_in[0];
    const float* h  = (const float*)d_in[1];
    const float* Wl = (const float*)d_in[2];
    const float* Wr = (const float*)d_in[3];
    const float* b  = (const float*)d_in[4];
    const int* src  = (const int*)d_in[5];
    const int* dst  = (const int*)d_in[6];
    float* out = (float*)d_out;

    cudaFuncSetAttribute(k_gemm1, cudaFuncAttributeMaxDynamicSharedMemorySize, GSMEM);
    cudaFuncSetAttribute(k_gemm2, cudaFuncAttributeMaxDynamicSharedMemorySize, GSMEM);

    const int ROWT = (NN + 127) / 128;
    const int WTOT = LL * 384 * 512 + LL * 128 * 256 + LL * 384;
    const int PREPN = EE + CONVN + LL * CONVN + WTOT;

    k_countscan<<<NCHUNK, 1024>>>(dst);
    k_prep<<<(PREPN + 255) / 256, 256>>>(src, dst, x, h, Wl, Wr, b);

    for (int l = 0; l < LL; l++) {
        const float* hl = h + (size_t)l * NN * DD;
        k_agg2<<<(NN * 32 + 255) / 256, 256>>>(l);
        dim3 g1(3, ROWT);
        k_gemm1<<<g1, 256, GSMEM>>>(hl, l);   // launch #4 <- ncu target
        k_agg1<<<(NN * 32 + 255) / 256, 256>>>();
        dim3 g2(1, ROWT);
        k_gemm2<<<g2, 256, GSMEM>>>(hl, out + (size_t)l * NN * DD, l);
    }

    k_zero_end<<<(NN + 255) / 256, 256>>>();
}

// round 13
// speedup vs baseline: 1.6792x; 1.0503x over previous
#include <cuda_runtime.h>
#include <cuda_fp16.h>
#include <math.h>
#include <stdint.h>

// Problem constants (fixed by setup_inputs)
#define NN 50000
#define EE 800000
#define DD 128
#define LL 2
#define NCHUNK ((NN + 1023) / 1024)
#define CONVN (NN * DD / 4)

// ---------------- scratch (static __device__ globals; no allocation) ----------------
__device__ float g_bias[LL * 384];
__device__ float g_invdeg[NN];
__device__ int g_rowptr[NN + 1];
__device__ int g_cursor[NN];
__device__ int g_esrc[EE];

__device__ __align__(16) __half g_Z[NN * DD];
__device__ __align__(16) __half g_HX[NN * DD];
__device__ __align__(16) __half g_inp[NN * DD];
__device__ __align__(16) __half g_h[LL * NN * DD];
__device__ __align__(16) __half g_agga[NN * DD];
__device__ __align__(16) __half g_aggb[NN * DD];
__device__ __align__(16) __half g_rh[NN * DD];
__device__ __align__(16) __half g_W1T[LL * 384 * 512];
__device__ __align__(16) __half g_W2T[LL * 128 * 256];

// ---------------- helpers ----------------
__device__ __forceinline__ uint32_t smem_u32(const void* p) {
    uint32_t a;
    asm("{ .reg .u64 t; cvta.to.shared.u64 t, %1; cvt.u32.u64 %0, t; }" : "=r"(a) : "l"(p));
    return a;
}
__device__ __forceinline__ void ldsm4(uint32_t* f, uint32_t addr) {
    asm volatile("ldmatrix.sync.aligned.m8n8.x4.shared.b16 {%0,%1,%2,%3}, [%4];"
                 : "=r"(f[0]), "=r"(f[1]), "=r"(f[2]), "=r"(f[3]) : "r"(addr));
}
__device__ __forceinline__ void mma16816(float* c, const uint32_t* a, uint32_t b0, uint32_t b1) {
    asm volatile(
        "mma.sync.aligned.m16n8k16.row.col.f32.f16.f16.f32 "
        "{%0,%1,%2,%3}, {%4,%5,%6,%7}, {%8,%9}, {%0,%1,%2,%3};"
        : "+f"(c[0]), "+f"(c[1]), "+f"(c[2]), "+f"(c[3])
        : "r"(a[0]), "r"(a[1]), "r"(a[2]), "r"(a[3]), "r"(b0), "r"(b1));
}
__device__ __forceinline__ void cpa16(uint32_t dst, const void* src, int sz) {
    asm volatile("cp.async.cg.shared.global [%0], [%1], 16, %2;"
                 :: "r"(dst), "l"(src), "r"(sz) : "memory");
}
#define CPA_COMMIT() asm volatile("cp.async.commit_group;" ::: "memory")
#define CPA_WAIT0()  asm volatile("cp.async.wait_group 0;" ::: "memory")

__device__ __forceinline__ void store_h4(__half* d, float4 v) {
    __half2 h0 = __floats2half2_rn(v.x, v.y);
    __half2 h1 = __floats2half2_rn(v.z, v.w);
    uint2 u;
    u.x = *(uint32_t*)&h0;
    u.y = *(uint32_t*)&h1;
    *(uint2*)d = u;
}
__device__ __forceinline__ void store_h2(__half* d, float a, float b) {
    __half2 hh = __floats2half2_rn(a, b);
    *(uint32_t*)d = *(uint32_t*)&hh;
}
__device__ __forceinline__ float sigf(float x) { return 1.0f / (1.0f + expf(-x)); }

// SMEM tile geometry: padded row stride 80B (conflict-free ldmatrix)
#define TROW 80
#define ATB (128 * TROW)           // A subtile: 128 rows x 32 cols  (10240)
#define BTB (64 * TROW)            // B subtile (gemm1): 64 rows x 32 cols (5120)
#define SUB1 (ATB + BTB)           // 15360
#define STAGE1 (2 * SUB1)          // K64 chunk for gemm1 (30720)
#define GSMEM1 (2 * STAGE1)        // 61440
// gemm2 keeps the 128-row B tile
#define SUB2 (2 * ATB)             // 20480
#define STAGE2 (2 * SUB2)          // 40960
#define GSMEM2 (2 * STAGE2)        // 81920

// precomputed per-thread tile-load state
struct Pre {
    uint32_t sm0, sm1;
    size_t a0, a1;
    int az0, az1;
    size_t b0, b1;
};

__device__ __forceinline__ Pre make_pre(int t, int row0, int col0, int strideB) {
    Pre p;
    int q = t & 3;
    int r0 = t >> 2, r1 = r0 + 64;
    p.sm0 = (uint32_t)(r0 * TROW + q * 16);
    p.sm1 = (uint32_t)(r1 * TROW + q * 16);
    int gr0 = row0 + r0, gr1 = row0 + r1;
    p.az0 = gr0 < NN ? 16 : 0;
    p.az1 = gr1 < NN ? 16 : 0;
    if (gr0 >= NN) gr0 = 0;
    if (gr1 >= NN) gr1 = 0;
    p.a0 = (size_t)gr0 * 128 + q * 8;
    p.a1 = (size_t)gr1 * 128 + q * 8;
    p.b0 = (size_t)(col0 + r0) * strideB + q * 8;
    p.b1 = (size_t)(col0 + r1) * strideB + q * 8;
    return p;
}

// gemm1 subtile pair: A 128x32 + B 64x32 (B row index = t>>2 in [0,64))
__device__ __forceinline__ void load_sub1(uint32_t buf,
                                          const __half* __restrict__ a,
                                          const __half* __restrict__ b,
                                          int colA, int colB, const Pre& p) {
    cpa16(buf + p.sm0,       a + p.a0 + colA, p.az0);
    cpa16(buf + p.sm1,       a + p.a1 + colA, p.az1);
    cpa16(buf + ATB + p.sm0, b + p.b0 + colB, 16);
}
__device__ __forceinline__ void load_stage1(uint32_t buf,
                                            const __half* __restrict__ a,
                                            const __half* __restrict__ b,
                                            int colA, int colB, const Pre& p) {
    load_sub1(buf,        a, b, colA,      colB,      p);
    load_sub1(buf + SUB1, a, b, colA + 32, colB + 32, p);
}

// gemm2 subtile pair: A 128x32 + B 128x32
__device__ __forceinline__ void load_sub2(uint32_t buf,
                                          const __half* __restrict__ a,
                                          const __half* __restrict__ b,
                                          int colA, int colB, const Pre& p) {
    cpa16(buf + p.sm0,       a + p.a0 + colA, p.az0);
    cpa16(buf + p.sm1,       a + p.a1 + colA, p.az1);
    cpa16(buf + ATB + p.sm0, b + p.b0 + colB, 16);
    cpa16(buf + ATB + p.sm1, b + p.b1 + colB, 16);
}
__device__ __forceinline__ void load_stage2(uint32_t buf,
                                            const __half* __restrict__ a,
                                            const __half* __restrict__ b,
                                            int colA, int colB, const Pre& p) {
    load_sub2(buf,        a, b, colA,      colB,      p);
    load_sub2(buf + SUB2, a, b, colA + 32, colB + 32, p);
}

// ---------------- CSR: fused count+scan ----------------
__global__ void __launch_bounds__(1024)
k_countscan(const int* __restrict__ dst) {
    __shared__ int hist[1024];
    __shared__ int ws[32];
    __shared__ int sbase;
    int b = blockIdx.x, t = threadIdx.x;
    int lane = t & 31, wid = t >> 5;
    hist[t] = 0;
    __syncthreads();

    int lo = b << 10;
    int pre = 0;
    const int4* d4 = (const int4*)dst;
    for (int e = t; e < EE / 4; e += 1024) {
        int4 v = __ldg(d4 + e);
        pre += (v.x < lo) + (v.y < lo) + (v.z < lo) + (v.w < lo);
        int dx;
        dx = v.x - lo; if ((unsigned)dx < 1024u) atomicAdd(&hist[dx], 1);
        dx = v.y - lo; if ((unsigned)dx < 1024u) atomicAdd(&hist[dx], 1);
        dx = v.z - lo; if ((unsigned)dx < 1024u) atomicAdd(&hist[dx], 1);
        dx = v.w - lo; if ((unsigned)dx < 1024u) atomicAdd(&hist[dx], 1);
    }
#pragma unroll
    for (int o = 16; o > 0; o >>= 1) pre += __shfl_down_sync(0xffffffffu, pre, o);
    if (lane == 0) ws[wid] = pre;
    __syncthreads();
    if (t < 32) {
        int s = ws[t];
#pragma unroll
        for (int o = 16; o > 0; o >>= 1) s += __shfl_down_sync(0xffffffffu, s, o);
        if (t == 0) sbase = s;
    }
    __syncthreads();
    int base = sbase;
    int v = hist[t];
    __syncthreads();

    int x = v;
#pragma unroll
    for (int o = 1; o < 32; o <<= 1) {
        int y = __shfl_up_sync(0xffffffffu, x, o);
        if (lane >= o) x += y;
    }
    if (lane == 31) ws[wid] = x;
    __syncthreads();
    if (wid == 0) {
        int s = ws[lane];
        int xs = s;
#pragma unroll
        for (int o = 1; o < 32; o <<= 1) {
            int y = __shfl_up_sync(0xffffffffu, xs, o);
            if (lane >= o) xs += y;
        }
        ws[lane] = xs - s;
    }
    __syncthreads();
    int incl = x + ws[wid];
    int i = lo + t;
    if (i < NN) {
        g_rowptr[i] = base + incl - v;
        g_invdeg[i] = 1.0f / fmaxf((float)v, 1.0f);
    }
    if (b == 0 && t == 0) g_rowptr[NN] = EE;
}

// ---------------- fused prep ----------------
__global__ void k_prep(const int* __restrict__ src, const int* __restrict__ dst,
                       const float* __restrict__ x, const float* __restrict__ h,
                       const float* __restrict__ Wl, const float* __restrict__ Wr,
                       const float* __restrict__ b) {
    const int W1TN = LL * 384 * 512;
    const int W2TN = LL * 128 * 256;
    int i = blockIdx.x * blockDim.x + threadIdx.x;
    if (i < EE) {
        int d = dst[i];
        int p = atomicAdd(&g_cursor[d], 1);
        g_esrc[g_rowptr[d] + p] = src[i];
    } else if (i < EE + CONVN) {
        int j = i - EE;
        float4 v = __ldg((const float4*)x + j);
        store_h4(g_inp + (size_t)j * 4, v);
    } else if (i < EE + CONVN + LL * CONVN) {
        int j = i - EE - CONVN;
        float4 v = __ldg((const float4*)h + j);
        store_h4(g_h + (size_t)j * 4, v);
    } else {
        int j = i - EE - CONVN - LL * CONVN;
        if (j < W1TN) {
            int l = j / (384 * 512);
            int rem = j % (384 * 512);
            int c = rem / 512, k = rem % 512;
            int cb = c >> 7, cc = c & 127;
            int s = k >> 7, kk = k & 127;
            float v = 0.0f;
            if (!(cb == 2 && s >= 2)) {
                int g = cb * 2 + (s >> 1);
                const float* W = (s & 1) ? Wr : Wl;
                v = W[(((size_t)l * 6 + g) * 128 + kk) * 128 + cc];
            }
            g_W1T[j] = __float2half_rn(v);
        } else if (j < W1TN + W2TN) {
            int j2 = j - W1TN;
            int l = j2 / (128 * 256);
            int rem = j2 % (128 * 256);
            int c = rem / 256, k = rem % 256;
            int s = k >> 7, kk = k & 127;
            const float* W = s ? Wr : Wl;
            float v = W[(((size_t)l * 6 + 5) * 128 + kk) * 128 + c];
            g_W2T[j2] = __float2half_rn(v);
        } else if (j < W1TN + W2TN + LL * 384) {
            int j2 = j - W1TN - W2TN;
            int l = j2 / 384;
            int c = j2 % 384;
            int cb = c >> 7, cc = c & 127;
            g_bias[j2] = b[(((size_t)l * 6 + cb * 2) * 128) + cc] +
                         b[(((size_t)l * 6 + cb * 2 + 1) * 128) + cc];
        }
    }
}

__global__ void k_zero_end() {
    int i = blockIdx.x * blockDim.x + threadIdx.x;
    if (i < NN) g_cursor[i] = 0;
}

// ---------------- aggregation ----------------
__global__ void k_agg2(int l) {
    int warp = (blockIdx.x * blockDim.x + threadIdx.x) >> 5;
    int lane = threadIdx.x & 31;
    if (warp >= NN) return;
    const __half* __restrict__ A = g_inp;
    const __half* __restrict__ B = g_h + (size_t)l * NN * DD;
    int e = g_rowptr[warp], end = g_rowptr[warp + 1];
    float4 aa = make_float4(0.f, 0.f, 0.f, 0.f);
    float4 ab = make_float4(0.f, 0.f, 0.f, 0.f);
#define ACC4(dst, v) do { \
        float2 _p0 = __half22float2(*(__half2*)&(v).x); \
        float2 _p1 = __half22float2(*(__half2*)&(v).y); \
        dst.x += _p0.x; dst.y += _p0.y; dst.z += _p1.x; dst.w += _p1.y; } while (0)
    for (; e + 3 < end; e += 4) {
        int s0 = g_esrc[e], s1 = g_esrc[e + 1], s2 = g_esrc[e + 2], s3 = g_esrc[e + 3];
        uint2 va0 = __ldg((const uint2*)(A + (size_t)s0 * DD) + lane);
        uint2 va1 = __ldg((const uint2*)(A + (size_t)s1 * DD) + lane);
        uint2 va2 = __ldg((const uint2*)(A + (size_t)s2 * DD) + lane);
        uint2 va3 = __ldg((const uint2*)(A + (size_t)s3 * DD) + lane);
        uint2 vb0 = __ldg((const uint2*)(B + (size_t)s0 * DD) + lane);
        uint2 vb1 = __ldg((const uint2*)(B + (size_t)s1 * DD) + lane);
        uint2 vb2 = __ldg((const uint2*)(B + (size_t)s2 * DD) + lane);
        uint2 vb3 = __ldg((const uint2*)(B + (size_t)s3 * DD) + lane);
        ACC4(aa, va0); ACC4(aa, va1); ACC4(aa, va2); ACC4(aa, va3);
        ACC4(ab, vb0); ACC4(ab, vb1); ACC4(ab, vb2); ACC4(ab, vb3);
    }
    for (; e < end; e++) {
        int s0 = g_esrc[e];
        uint2 va0 = __ldg((const uint2*)(A + (size_t)s0 * DD) + lane);
        uint2 vb0 = __ldg((const uint2*)(B + (size_t)s0 * DD) + lane);
        ACC4(aa, va0); ACC4(ab, vb0);
    }
    float sc = g_invdeg[warp];
    aa.x *= sc; aa.y *= sc; aa.z *= sc; aa.w *= sc;
    ab.x *= sc; ab.y *= sc; ab.z *= sc; ab.w *= sc;
    size_t o = (size_t)warp * DD + lane * 4;
    store_h4(g_agga + o, aa);
    store_h4(g_aggb + o, ab);
}

__global__ void k_agg1() {
    int warp = (blockIdx.x * blockDim.x + threadIdx.x) >> 5;
    int lane = threadIdx.x & 31;
    if (warp >= NN) return;
    int e = g_rowptr[warp], end = g_rowptr[warp + 1];
    float4 aa = make_float4(0.f, 0.f, 0.f, 0.f);
    for (; e + 3 < end; e += 4) {
        int s0 = g_esrc[e], s1 = g_esrc[e + 1], s2 = g_esrc[e + 2], s3 = g_esrc[e + 3];
        uint2 v0 = __ldg((const uint2*)(g_rh + (size_t)s0 * DD) + lane);
        uint2 v1 = __ldg((const uint2*)(g_rh + (size_t)s1 * DD) + lane);
        uint2 v2 = __ldg((const uint2*)(g_rh + (size_t)s2 * DD) + lane);
        uint2 v3 = __ldg((const uint2*)(g_rh + (size_t)s3 * DD) + lane);
        ACC4(aa, v0); ACC4(aa, v1); ACC4(aa, v2); ACC4(aa, v3);
    }
    for (; e < end; e++) {
        int s0 = g_esrc[e];
        uint2 v0 = __ldg((const uint2*)(g_rh + (size_t)s0 * DD) + lane);
        ACC4(aa, v0);
    }
    float sc = g_invdeg[warp];
    aa.x *= sc; aa.y *= sc; aa.z *= sc; aa.w *= sc;
    store_h4(g_agga + (size_t)warp * DD + lane * 4, aa);
}
#undef ACC4

// ---------------- GEMM1: CTA 128x64, 8 warps (4x2), warp tile 32x32, 3 CTAs/SM ----------------
// grid = (6, ROWT). cb64 = blockIdx.x; epilogue branch cb = cb64>>1.
// cb64 < 4 (z,r): 8 K64 chunks; cb64 in {4,5} (hx): 4 chunks.
__device__ __forceinline__ void gemm_sub1(uint32_t sA, uint32_t lsm_a, uint32_t lsm_b,
                                          float acc[2][4][4]) {
    uint32_t sB = sA + ATB;
#pragma unroll
    for (int kb = 0; kb < 2; kb++) {
        uint32_t ko = kb * 32;
        uint32_t Af[2][4], Bf[2][4];
        ldsm4(Af[0], sA + lsm_a + ko);
        ldsm4(Af[1], sA + lsm_a + ko + 16 * TROW);
        ldsm4(Bf[0], sB + lsm_b + ko);
        ldsm4(Bf[1], sB + lsm_b + ko + 16 * TROW);
#pragma unroll
        for (int mt = 0; mt < 2; mt++)
#pragma unroll
            for (int nt = 0; nt < 4; nt++) {
                int ng = nt >> 1, o = nt & 1;
                mma16816(acc[mt][nt], Af[mt], Bf[ng][o], Bf[ng][o + 2]);
            }
    }
}

__global__ void __launch_bounds__(256, 3)
k_gemm1(const float* __restrict__ hl, int l) {
    extern __shared__ __align__(16) char smdyn[];
    uint32_t sb = smem_u32(smdyn);
    int t = threadIdx.x;
    int row0 = blockIdx.y * 128;
    int cb64 = blockIdx.x;
    int col0 = cb64 * 64;
    int cb = cb64 >> 1;
    const int NC = (cb == 2) ? 4 : 8;

    const __half* __restrict__ W = g_W1T + (size_t)l * 384 * 512;
    const __half* segs[4] = { g_agga, g_inp, g_aggb, g_h + (size_t)l * NN * DD };

    const Pre p = make_pre(t, row0, col0, 512);
    int lane = t & 31, wid = t >> 5;
    int wm = wid & 3, wn = wid >> 2;
    uint32_t rsel = (uint32_t)(lane & 15) * TROW + (uint32_t)(lane >> 4) * 16;
    uint32_t lsm_a = (uint32_t)(wm * 32) * TROW + rsel;
    uint32_t lsm_b = (uint32_t)(wn * 32) * TROW + rsel;

    float acc[2][4][4];
#pragma unroll
    for (int i = 0; i < 2; i++)
#pragma unroll
        for (int j = 0; j < 4; j++)
#pragma unroll
            for (int q = 0; q < 4; q++) acc[i][j][q] = 0.0f;

    load_stage1(sb, segs[0], W, 0, 0, p);
    CPA_COMMIT();
    for (int c = 0; c < NC; c++) {
        CPA_WAIT0();
        __syncthreads();
        if (c + 1 < NC) {
            int cn = c + 1;
            int seg = cn >> 1, colA = (cn & 1) * 64, colB = cn * 64;
            load_stage1(sb + (cn & 1) * STAGE1, segs[seg], W, colA, colB, p);
            CPA_COMMIT();
        }
        uint32_t buf = sb + (c & 1) * STAGE1;
        gemm_sub1(buf, lsm_a, lsm_b, acc);
        gemm_sub1(buf + SUB1, lsm_a, lsm_b, acc);
    }

    // epilogue
    const float* bias = g_bias + l * 384;
#pragma unroll
    for (int mt = 0; mt < 2; mt++)
#pragma unroll
        for (int nt = 0; nt < 4; nt++) {
            int row = row0 + wm * 32 + mt * 16 + (lane >> 2);
            int col = col0 + wn * 32 + nt * 8 + (lane & 3) * 2;
            float b0 = __ldg(bias + col), b1 = __ldg(bias + col + 1);
            int ccol = col & 127;
#pragma unroll
            for (int half = 0; half < 2; half++) {
                int r = row + half * 8;
                if (r >= NN) continue;
                float v0 = acc[mt][nt][half * 2 + 0] + b0;
                float v1 = acc[mt][nt][half * 2 + 1] + b1;
                size_t idx = (size_t)r * 128 + ccol;
                if (cb == 0) {
                    store_h2(g_Z + idx, sigf(v0), sigf(v1));
                } else if (cb == 1) {
                    float h0 = hl[idx], h1 = hl[idx + 1];
                    store_h2(g_rh + idx, sigf(v0) * h0, sigf(v1) * h1);
                } else {
                    store_h2(g_HX + idx, v0, v1);
                }
            }
        }
}

// ---------------- GEMM2: [N,256]x[256,128] fused GRU mix (unchanged structure) ----------------
__device__ __forceinline__ void gemm_sub2(uint32_t sA, uint32_t lsm_a, uint32_t lsm_b,
                                          float acc[2][8][4]) {
    uint32_t sB = sA + ATB;
#pragma unroll
    for (int kb = 0; kb < 2; kb++) {
        uint32_t ko = kb * 32;
        uint32_t aoff = lsm_a + ko;
        uint32_t boff = lsm_b + ko;
        uint32_t Af[2][4], Bf[4][4];
        ldsm4(Af[0], sA + aoff);
        ldsm4(Af[1], sA + aoff + 16 * TROW);
#pragma unroll
        for (int ng = 0; ng < 4; ng++) ldsm4(Bf[ng], sB + boff + ng * 16 * TROW);
#pragma unroll
        for (int mt = 0; mt < 2; mt++)
#pragma unroll
            for (int nt = 0; nt < 8; nt++) {
                int ng = nt >> 1, o = nt & 1;
                mma16816(acc[mt][nt], Af[mt], Bf[ng][o], Bf[ng][o + 2]);
            }
    }
}

__global__ void __launch_bounds__(256, 2)
k_gemm2(const float* __restrict__ hl, float* __restrict__ out, int l) {
    extern __shared__ __align__(16) char smdyn[];
    uint32_t sb = smem_u32(smdyn);
    int t = threadIdx.x;
    int row0 = blockIdx.y * 128;

    const __half* __restrict__ W = g_W2T + (size_t)l * 128 * 256;
    const __half* segs[2] = { g_agga, g_rh };

    const Pre p = make_pre(t, row0, 0, 256);
    int lane = t & 31, wid = t >> 5;
    int wm = wid & 3, wn = wid >> 2;
    uint32_t rsel = (uint32_t)(lane & 15) * TROW + (uint32_t)(lane >> 4) * 16;
    uint32_t lsm_a = (uint32_t)(wm * 32) * TROW + rsel;
    uint32_t lsm_b = (uint32_t)(wn * 64) * TROW + rsel;

    float acc[2][8][4];
#pragma unroll
    for (int i = 0; i < 2; i++)
#pragma unroll
        for (int j = 0; j < 8; j++)
#pragma unroll
            for (int q = 0; q < 4; q++) acc[i][j][q] = 0.0f;

    load_stage2(sb, segs[0], W, 0, 0, p);
    CPA_COMMIT();
    for (int c = 0; c < 4; c++) {
        CPA_WAIT0();
        __syncthreads();
        if (c + 1 < 4) {
            int cn = c + 1;
            int seg = cn >> 1, colA = (cn & 1) * 64, colB = cn * 64;
            load_stage2(sb + (cn & 1) * STAGE2, segs[seg], W, colA, colB, p);
            CPA_COMMIT();
        }
        uint32_t buf = sb + (c & 1) * STAGE2;
        gemm_sub2(buf, lsm_a, lsm_b, acc);
        gemm_sub2(buf + SUB2, lsm_a, lsm_b, acc);
    }

#pragma unroll
    for (int mt = 0; mt < 2; mt++)
#pragma unroll
        for (int nt = 0; nt < 8; nt++) {
            int row = row0 + wm * 32 + mt * 16 + (lane >> 2);
            int col = wn * 64 + nt * 8 + (lane & 3) * 2;
#pragma unroll
            for (int half = 0; half < 2; half++) {
                int r = row + half * 8;
                if (r >= NN) continue;
                size_t idx = (size_t)r * 128 + col;
                float2 hx = __half22float2(*(const __half2*)(g_HX + idx));
                float2 zz = __half22float2(*(const __half2*)(g_Z + idx));
                float h0 = hl[idx], h1 = hl[idx + 1];
                float ht0 = tanhf(acc[mt][nt][half * 2 + 0] + hx.x);
                float ht1 = tanhf(acc[mt][nt][half * 2 + 1] + hx.y);
                float o0 = zz.x * h0 + (1.0f - zz.x) * ht0;
                float o1 = zz.y * h1 + (1.0f - zz.y) * ht1;
                *(float2*)(out + idx) = make_float2(o0, o1);
                store_h2(g_inp + idx, o0, o1);
            }
        }
}

// ---------------- launch ----------------
extern "C" void kernel_launch(void* const* d_in, const int* in_sizes, int n_in,
                              void* d_out, int out_size) {
    const float* x  = (const float*)d_in[0];
    const float* h  = (const float*)d_in[1];
    const float* Wl = (const float*)d_in[2];
    const float* Wr = (const float*)d_in[3];
    const float* b  = (const float*)d_in[4];
    const int* src  = (const int*)d_in[5];
    const int* dst  = (const int*)d_in[6];
    float* out = (float*)d_out;

    cudaFuncSetAttribute(k_gemm1, cudaFuncAttributeMaxDynamicSharedMemorySize, GSMEM1);
    cudaFuncSetAttribute(k_gemm2, cudaFuncAttributeMaxDynamicSharedMemorySize, GSMEM2);

    const int ROWT = (NN + 127) / 128;
    const int WTOT = LL * 384 * 512 + LL * 128 * 256 + LL * 384;
    const int PREPN = EE + CONVN + LL * CONVN + WTOT;

    k_countscan<<<NCHUNK, 1024>>>(dst);
    k_prep<<<(PREPN + 255) / 256, 256>>>(src, dst, x, h, Wl, Wr, b);

    for (int l = 0; l < LL; l++) {
        const float* hl = h + (size_t)l * NN * DD;
        k_agg2<<<(NN * 32 + 255) / 256, 256>>>(l);
        dim3 g1(6, ROWT);
        k_gemm1<<<g1, 256, GSMEM1>>>(hl, l);   // launch #4 <- ncu target
        k_agg1<<<(NN * 32 + 255) / 256, 256>>>();
        dim3 g2(1, ROWT);
        k_gemm2<<<g2, 256, GSMEM2>>>(hl, out + (size_t)l * NN * DD, l);
    }

    k_zero_end<<<(NN + 255) / 256, 256>>>();
}

// round 14
// speedup vs baseline: 1.7243x; 1.0268x over previous
#include <cuda_runtime.h>
#include <cuda_fp16.h>
#include <math.h>
#include <stdint.h>

// Problem constants (fixed by setup_inputs)
#define NN 50000
#define EE 800000
#define DD 128
#define LL 2
#define NCHUNK ((NN + 1023) / 1024)
#define CONVN (NN * DD / 4)

// ---------------- scratch (static __device__ globals; no allocation) ----------------
__device__ float g_bias[LL * 384];
__device__ float g_invdeg[NN];
__device__ int g_rowptr[NN + 1];
__device__ int g_cursor[NN];
__device__ int g_esrc[EE];

__device__ __align__(16) __half g_Z[NN * DD];
__device__ __align__(16) __half g_HX[NN * DD];
__device__ __align__(16) __half g_inp[NN * DD];
__device__ __align__(16) __half g_h[LL * NN * DD];
__device__ __align__(16) __half g_agga[NN * DD];
__device__ __align__(16) __half g_aggb[NN * DD];
__device__ __align__(16) __half g_rh[NN * DD];
__device__ __align__(16) __half g_W1T[LL * 384 * 512];
__device__ __align__(16) __half g_W2T[LL * 128 * 256];

// ---------------- helpers ----------------
__device__ __forceinline__ uint32_t smem_u32(const void* p) {
    uint32_t a;
    asm("{ .reg .u64 t; cvta.to.shared.u64 t, %1; cvt.u32.u64 %0, t; }" : "=r"(a) : "l"(p));
    return a;
}
__device__ __forceinline__ void ldsm4(uint32_t* f, uint32_t addr) {
    asm volatile("ldmatrix.sync.aligned.m8n8.x4.shared.b16 {%0,%1,%2,%3}, [%4];"
                 : "=r"(f[0]), "=r"(f[1]), "=r"(f[2]), "=r"(f[3]) : "r"(addr));
}
__device__ __forceinline__ void mma16816(float* c, const uint32_t* a, uint32_t b0, uint32_t b1) {
    asm volatile(
        "mma.sync.aligned.m16n8k16.row.col.f32.f16.f16.f32 "
        "{%0,%1,%2,%3}, {%4,%5,%6,%7}, {%8,%9}, {%0,%1,%2,%3};"
        : "+f"(c[0]), "+f"(c[1]), "+f"(c[2]), "+f"(c[3])
        : "r"(a[0]), "r"(a[1]), "r"(a[2]), "r"(a[3]), "r"(b0), "r"(b1));
}
__device__ __forceinline__ void cpa16(uint32_t dst, const void* src, int sz) {
    asm volatile("cp.async.cg.shared.global [%0], [%1], 16, %2;"
                 :: "r"(dst), "l"(src), "r"(sz) : "memory");
}
#define CPA_COMMIT() asm volatile("cp.async.commit_group;" ::: "memory")
#define CPA_WAIT0()  asm volatile("cp.async.wait_group 0;" ::: "memory")

__device__ __forceinline__ void store_h4(__half* d, float4 v) {
    __half2 h0 = __floats2half2_rn(v.x, v.y);
    __half2 h1 = __floats2half2_rn(v.z, v.w);
    uint2 u;
    u.x = *(uint32_t*)&h0;
    u.y = *(uint32_t*)&h1;
    *(uint2*)d = u;
}
__device__ __forceinline__ void store_h2(__half* d, float a, float b) {
    __half2 hh = __floats2half2_rn(a, b);
    *(uint32_t*)d = *(uint32_t*)&hh;
}
// fast MUFU-path transcendentals (rel err ~1e-6, invisible vs fp16 path error)
__device__ __forceinline__ float sigf(float x) { return 1.0f / (1.0f + __expf(-x)); }
__device__ __forceinline__ float tanh_fast(float x) {
    float t = __expf(2.0f * x);          // +inf for large x, 0 for very negative
    return 1.0f - 2.0f / (t + 1.0f);     // -> 1 and -1 at the limits
}

// SMEM tile geometry: padded row stride 80B (conflict-free ldmatrix)
#define TROW 80
#define ATB (128 * TROW)           // A subtile: 128 rows x 32 cols  (10240)
#define BTB (64 * TROW)            // B subtile: 64 rows x 32 cols (5120)
#define SUB1 (ATB + BTB)           // 15360
#define STAGE1 (2 * SUB1)          // K64 chunk (30720)
#define GSMEM1 (2 * STAGE1)        // 61440

// precomputed per-thread tile-load state
struct Pre {
    uint32_t sm0, sm1;
    size_t a0, a1;
    int az0, az1;
    size_t b0, b1;
};

__device__ __forceinline__ Pre make_pre(int t, int row0, int col0, int strideB) {
    Pre p;
    int q = t & 3;
    int r0 = t >> 2, r1 = r0 + 64;
    p.sm0 = (uint32_t)(r0 * TROW + q * 16);
    p.sm1 = (uint32_t)(r1 * TROW + q * 16);
    int gr0 = row0 + r0, gr1 = row0 + r1;
    p.az0 = gr0 < NN ? 16 : 0;
    p.az1 = gr1 < NN ? 16 : 0;
    if (gr0 >= NN) gr0 = 0;
    if (gr1 >= NN) gr1 = 0;
    p.a0 = (size_t)gr0 * 128 + q * 8;
    p.a1 = (size_t)gr1 * 128 + q * 8;
    p.b0 = (size_t)(col0 + r0) * strideB + q * 8;
    p.b1 = (size_t)(col0 + r1) * strideB + q * 8;
    return p;
}

// subtile pair: A 128x32 + B 64x32 (B row index = t>>2 in [0,64))
__device__ __forceinline__ void load_sub1(uint32_t buf,
                                          const __half* __restrict__ a,
                                          const __half* __restrict__ b,
                                          int colA, int colB, const Pre& p) {
    cpa16(buf + p.sm0,       a + p.a0 + colA, p.az0);
    cpa16(buf + p.sm1,       a + p.a1 + colA, p.az1);
    cpa16(buf + ATB + p.sm0, b + p.b0 + colB, 16);
}
__device__ __forceinline__ void load_stage1(uint32_t buf,
                                            const __half* __restrict__ a,
                                            const __half* __restrict__ b,
                                            int colA, int colB, const Pre& p) {
    load_sub1(buf,        a, b, colA,      colB,      p);
    load_sub1(buf + SUB1, a, b, colA + 32, colB + 32, p);
}

// ---------------- CSR: fused count+scan ----------------
__global__ void __launch_bounds__(1024)
k_countscan(const int* __restrict__ dst) {
    __shared__ int hist[1024];
    __shared__ int ws[32];
    __shared__ int sbase;
    int b = blockIdx.x, t = threadIdx.x;
    int lane = t & 31, wid = t >> 5;
    hist[t] = 0;
    __syncthreads();

    int lo = b << 10;
    int pre = 0;
    const int4* d4 = (const int4*)dst;
    for (int e = t; e < EE / 4; e += 1024) {
        int4 v = __ldg(d4 + e);
        pre += (v.x < lo) + (v.y < lo) + (v.z < lo) + (v.w < lo);
        int dx;
        dx = v.x - lo; if ((unsigned)dx < 1024u) atomicAdd(&hist[dx], 1);
        dx = v.y - lo; if ((unsigned)dx < 1024u) atomicAdd(&hist[dx], 1);
        dx = v.z - lo; if ((unsigned)dx < 1024u) atomicAdd(&hist[dx], 1);
        dx = v.w - lo; if ((unsigned)dx < 1024u) atomicAdd(&hist[dx], 1);
    }
#pragma unroll
    for (int o = 16; o > 0; o >>= 1) pre += __shfl_down_sync(0xffffffffu, pre, o);
    if (lane == 0) ws[wid] = pre;
    __syncthreads();
    if (t < 32) {
        int s = ws[t];
#pragma unroll
        for (int o = 16; o > 0; o >>= 1) s += __shfl_down_sync(0xffffffffu, s, o);
        if (t == 0) sbase = s;
    }
    __syncthreads();
    int base = sbase;
    int v = hist[t];
    __syncthreads();

    int x = v;
#pragma unroll
    for (int o = 1; o < 32; o <<= 1) {
        int y = __shfl_up_sync(0xffffffffu, x, o);
        if (lane >= o) x += y;
    }
    if (lane == 31) ws[wid] = x;
    __syncthreads();
    if (wid == 0) {
        int s = ws[lane];
        int xs = s;
#pragma unroll
        for (int o = 1; o < 32; o <<= 1) {
            int y = __shfl_up_sync(0xffffffffu, xs, o);
            if (lane >= o) xs += y;
        }
        ws[lane] = xs - s;
    }
    __syncthreads();
    int incl = x + ws[wid];
    int i = lo + t;
    if (i < NN) {
        g_rowptr[i] = base + incl - v;
        g_invdeg[i] = 1.0f / fmaxf((float)v, 1.0f);
    }
    if (b == 0 && t == 0) g_rowptr[NN] = EE;
}

// ---------------- fused prep ----------------
__global__ void k_prep(const int* __restrict__ src, const int* __restrict__ dst,
                       const float* __restrict__ x, const float* __restrict__ h,
                       const float* __restrict__ Wl, const float* __restrict__ Wr,
                       const float* __restrict__ b) {
    const int W1TN = LL * 384 * 512;
    const int W2TN = LL * 128 * 256;
    int i = blockIdx.x * blockDim.x + threadIdx.x;
    if (i < EE) {
        int d = dst[i];
        int p = atomicAdd(&g_cursor[d], 1);
        g_esrc[g_rowptr[d] + p] = src[i];
    } else if (i < EE + CONVN) {
        int j = i - EE;
        float4 v = __ldg((const float4*)x + j);
        store_h4(g_inp + (size_t)j * 4, v);
    } else if (i < EE + CONVN + LL * CONVN) {
        int j = i - EE - CONVN;
        float4 v = __ldg((const float4*)h + j);
        store_h4(g_h + (size_t)j * 4, v);
    } else {
        int j = i - EE - CONVN - LL * CONVN;
        if (j < W1TN) {
            int l = j / (384 * 512);
            int rem = j % (384 * 512);
            int c = rem / 512, k = rem % 512;
            int cb = c >> 7, cc = c & 127;
            int s = k >> 7, kk = k & 127;
            float v = 0.0f;
            if (!(cb == 2 && s >= 2)) {
                int g = cb * 2 + (s >> 1);
                const float* W = (s & 1) ? Wr : Wl;
                v = W[(((size_t)l * 6 + g) * 128 + kk) * 128 + cc];
            }
            g_W1T[j] = __float2half_rn(v);
        } else if (j < W1TN + W2TN) {
            int j2 = j - W1TN;
            int l = j2 / (128 * 256);
            int rem = j2 % (128 * 256);
            int c = rem / 256, k = rem % 256;
            int s = k >> 7, kk = k & 127;
            const float* W = s ? Wr : Wl;
            float v = W[(((size_t)l * 6 + 5) * 128 + kk) * 128 + c];
            g_W2T[j2] = __float2half_rn(v);
        } else if (j < W1TN + W2TN + LL * 384) {
            int j2 = j - W1TN - W2TN;
            int l = j2 / 384;
            int c = j2 % 384;
            int cb = c >> 7, cc = c & 127;
            g_bias[j2] = b[(((size_t)l * 6 + cb * 2) * 128) + cc] +
                         b[(((size_t)l * 6 + cb * 2 + 1) * 128) + cc];
        }
    }
}

__global__ void k_zero_end() {
    int i = blockIdx.x * blockDim.x + threadIdx.x;
    if (i < NN) g_cursor[i] = 0;
}

// ---------------- aggregation ----------------
__global__ void k_agg2(int l) {
    int warp = (blockIdx.x * blockDim.x + threadIdx.x) >> 5;
    int lane = threadIdx.x & 31;
    if (warp >= NN) return;
    const __half* __restrict__ A = g_inp;
    const __half* __restrict__ B = g_h + (size_t)l * NN * DD;
    int e = g_rowptr[warp], end = g_rowptr[warp + 1];
    float4 aa = make_float4(0.f, 0.f, 0.f, 0.f);
    float4 ab = make_float4(0.f, 0.f, 0.f, 0.f);
#define ACC4(dst, v) do { \
        float2 _p0 = __half22float2(*(__half2*)&(v).x); \
        float2 _p1 = __half22float2(*(__half2*)&(v).y); \
        dst.x += _p0.x; dst.y += _p0.y; dst.z += _p1.x; dst.w += _p1.y; } while (0)
    for (; e + 3 < end; e += 4) {
        int s0 = g_esrc[e], s1 = g_esrc[e + 1], s2 = g_esrc[e + 2], s3 = g_esrc[e + 3];
        uint2 va0 = __ldg((const uint2*)(A + (size_t)s0 * DD) + lane);
        uint2 va1 = __ldg((const uint2*)(A + (size_t)s1 * DD) + lane);
        uint2 va2 = __ldg((const uint2*)(A + (size_t)s2 * DD) + lane);
        uint2 va3 = __ldg((const uint2*)(A + (size_t)s3 * DD) + lane);
        uint2 vb0 = __ldg((const uint2*)(B + (size_t)s0 * DD) + lane);
        uint2 vb1 = __ldg((const uint2*)(B + (size_t)s1 * DD) + lane);
        uint2 vb2 = __ldg((const uint2*)(B + (size_t)s2 * DD) + lane);
        uint2 vb3 = __ldg((const uint2*)(B + (size_t)s3 * DD) + lane);
        ACC4(aa, va0); ACC4(aa, va1); ACC4(aa, va2); ACC4(aa, va3);
        ACC4(ab, vb0); ACC4(ab, vb1); ACC4(ab, vb2); ACC4(ab, vb3);
    }
    for (; e < end; e++) {
        int s0 = g_esrc[e];
        uint2 va0 = __ldg((const uint2*)(A + (size_t)s0 * DD) + lane);
        uint2 vb0 = __ldg((const uint2*)(B + (size_t)s0 * DD) + lane);
        ACC4(aa, va0); ACC4(ab, vb0);
    }
    float sc = g_invdeg[warp];
    aa.x *= sc; aa.y *= sc; aa.z *= sc; aa.w *= sc;
    ab.x *= sc; ab.y *= sc; ab.z *= sc; ab.w *= sc;
    size_t o = (size_t)warp * DD + lane * 4;
    store_h4(g_agga + o, aa);
    store_h4(g_aggb + o, ab);
}

__global__ void k_agg1() {
    int warp = (blockIdx.x * blockDim.x + threadIdx.x) >> 5;
    int lane = threadIdx.x & 31;
    if (warp >= NN) return;
    int e = g_rowptr[warp], end = g_rowptr[warp + 1];
    float4 aa = make_float4(0.f, 0.f, 0.f, 0.f);
    for (; e + 3 < end; e += 4) {
        int s0 = g_esrc[e], s1 = g_esrc[e + 1], s2 = g_esrc[e + 2], s3 = g_esrc[e + 3];
        uint2 v0 = __ldg((const uint2*)(g_rh + (size_t)s0 * DD) + lane);
        uint2 v1 = __ldg((const uint2*)(g_rh + (size_t)s1 * DD) + lane);
        uint2 v2 = __ldg((const uint2*)(g_rh + (size_t)s2 * DD) + lane);
        uint2 v3 = __ldg((const uint2*)(g_rh + (size_t)s3 * DD) + lane);
        ACC4(aa, v0); ACC4(aa, v1); ACC4(aa, v2); ACC4(aa, v3);
    }
    for (; e < end; e++) {
        int s0 = g_esrc[e];
        uint2 v0 = __ldg((const uint2*)(g_rh + (size_t)s0 * DD) + lane);
        ACC4(aa, v0);
    }
    float sc = g_invdeg[warp];
    aa.x *= sc; aa.y *= sc; aa.z *= sc; aa.w *= sc;
    store_h4(g_agga + (size_t)warp * DD + lane * 4, aa);
}
#undef ACC4

// ---------------- HMMA core: 32x32 warp tile, one 32-col subtile pair ----------------
__device__ __forceinline__ void gemm_sub1(uint32_t sA, uint32_t lsm_a, uint32_t lsm_b,
                                          float acc[2][4][4]) {
    uint32_t sB = sA + ATB;
#pragma unroll
    for (int kb = 0; kb < 2; kb++) {
        uint32_t ko = kb * 32;
        uint32_t Af[2][4], Bf[2][4];
        ldsm4(Af[0], sA + lsm_a + ko);
        ldsm4(Af[1], sA + lsm_a + ko + 16 * TROW);
        ldsm4(Bf[0], sB + lsm_b + ko);
        ldsm4(Bf[1], sB + lsm_b + ko + 16 * TROW);
#pragma unroll
        for (int mt = 0; mt < 2; mt++)
#pragma unroll
            for (int nt = 0; nt < 4; nt++) {
                int ng = nt >> 1, o = nt & 1;
                mma16816(acc[mt][nt], Af[mt], Bf[ng][o], Bf[ng][o + 2]);
            }
    }
}

// ---------------- GEMM1: CTA 128x64, warp tile 32x32, 3 CTAs/SM ----------------
__global__ void __launch_bounds__(256, 3)
k_gemm1(const float* __restrict__ hl, int l) {
    extern __shared__ __align__(16) char smdyn[];
    uint32_t sb = smem_u32(smdyn);
    int t = threadIdx.x;
    int row0 = blockIdx.y * 128;
    int cb64 = blockIdx.x;
    int col0 = cb64 * 64;
    int cb = cb64 >> 1;
    const int NC = (cb == 2) ? 4 : 8;

    const __half* __restrict__ W = g_W1T + (size_t)l * 384 * 512;
    const __half* segs[4] = { g_agga, g_inp, g_aggb, g_h + (size_t)l * NN * DD };

    const Pre p = make_pre(t, row0, col0, 512);
    int lane = t & 31, wid = t >> 5;
    int wm = wid & 3, wn = wid >> 2;
    uint32_t rsel = (uint32_t)(lane & 15) * TROW + (uint32_t)(lane >> 4) * 16;
    uint32_t lsm_a = (uint32_t)(wm * 32) * TROW + rsel;
    uint32_t lsm_b = (uint32_t)(wn * 32) * TROW + rsel;

    float acc[2][4][4];
#pragma unroll
    for (int i = 0; i < 2; i++)
#pragma unroll
        for (int j = 0; j < 4; j++)
#pragma unroll
            for (int q = 0; q < 4; q++) acc[i][j][q] = 0.0f;

    load_stage1(sb, segs[0], W, 0, 0, p);
    CPA_COMMIT();
    for (int c = 0; c < NC; c++) {
        CPA_WAIT0();
        __syncthreads();
        if (c + 1 < NC) {
            int cn = c + 1;
            int seg = cn >> 1, colA = (cn & 1) * 64, colB = cn * 64;
            load_stage1(sb + (cn & 1) * STAGE1, segs[seg], W, colA, colB, p);
            CPA_COMMIT();
        }
        uint32_t buf = sb + (c & 1) * STAGE1;
        gemm_sub1(buf, lsm_a, lsm_b, acc);
        gemm_sub1(buf + SUB1, lsm_a, lsm_b, acc);
    }

    // epilogue
    const float* bias = g_bias + l * 384;
#pragma unroll
    for (int mt = 0; mt < 2; mt++)
#pragma unroll
        for (int nt = 0; nt < 4; nt++) {
            int row = row0 + wm * 32 + mt * 16 + (lane >> 2);
            int col = col0 + wn * 32 + nt * 8 + (lane & 3) * 2;
            float b0 = __ldg(bias + col), b1 = __ldg(bias + col + 1);
            int ccol = col & 127;
#pragma unroll
            for (int half = 0; half < 2; half++) {
                int r = row + half * 8;
                if (r >= NN) continue;
                float v0 = acc[mt][nt][half * 2 + 0] + b0;
                float v1 = acc[mt][nt][half * 2 + 1] + b1;
                size_t idx = (size_t)r * 128 + ccol;
                if (cb == 0) {
                    store_h2(g_Z + idx, sigf(v0), sigf(v1));
                } else if (cb == 1) {
                    float h0 = hl[idx], h1 = hl[idx + 1];
                    store_h2(g_rh + idx, sigf(v0) * h0, sigf(v1) * h1);
                } else {
                    store_h2(g_HX + idx, v0, v1);
                }
            }
        }
}

// ---------------- GEMM2: CTA 128x64, warp tile 32x32, 3 CTAs/SM, fused GRU mix ----------------
__global__ void __launch_bounds__(256, 3)
k_gemm2(const float* __restrict__ hl, float* __restrict__ out, int l) {
    extern __shared__ __align__(16) char smdyn[];
    uint32_t sb = smem_u32(smdyn);
    int t = threadIdx.x;
    int row0 = blockIdx.y * 128;
    int col0 = blockIdx.x * 64;

    const __half* __restrict__ W = g_W2T + (size_t)l * 128 * 256;
    const __half* segs[2] = { g_agga, g_rh };

    const Pre p = make_pre(t, row0, col0, 256);
    int lane = t & 31, wid = t >> 5;
    int wm = wid & 3, wn = wid >> 2;
    uint32_t rsel = (uint32_t)(lane & 15) * TROW + (uint32_t)(lane >> 4) * 16;
    uint32_t lsm_a = (uint32_t)(wm * 32) * TROW + rsel;
    uint32_t lsm_b = (uint32_t)(wn * 32) * TROW + rsel;

    float acc[2][4][4];
#pragma unroll
    for (int i = 0; i < 2; i++)
#pragma unroll
        for (int j = 0; j < 4; j++)
#pragma unroll
            for (int q = 0; q < 4; q++) acc[i][j][q] = 0.0f;

    load_stage1(sb, segs[0], W, 0, 0, p);
    CPA_COMMIT();
    for (int c = 0; c < 4; c++) {
        CPA_WAIT0();
        __syncthreads();
        if (c + 1 < 4) {
            int cn = c + 1;
            int seg = cn >> 1, colA = (cn & 1) * 64, colB = cn * 64;
            load_stage1(sb + (cn & 1) * STAGE1, segs[seg], W, colA, colB, p);
            CPA_COMMIT();
        }
        uint32_t buf = sb + (c & 1) * STAGE1;
        gemm_sub1(buf, lsm_a, lsm_b, acc);
        gemm_sub1(buf + SUB1, lsm_a, lsm_b, acc);
    }

#pragma unroll
    for (int mt = 0; mt < 2; mt++)
#pragma unroll
        for (int nt = 0; nt < 4; nt++) {
            int row = row0 + wm * 32 + mt * 16 + (lane >> 2);
            int col = col0 + wn * 32 + nt * 8 + (lane & 3) * 2;
#pragma unroll
            for (int half = 0; half < 2; half++) {
                int r = row + half * 8;
                if (r >= NN) continue;
                size_t idx = (size_t)r * 128 + col;
                float2 hx = __half22float2(*(const __half2*)(g_HX + idx));
                float2 zz = __half22float2(*(const __half2*)(g_Z + idx));
                float h0 = hl[idx], h1 = hl[idx + 1];
                float ht0 = tanh_fast(acc[mt][nt][half * 2 + 0] + hx.x);
                float ht1 = tanh_fast(acc[mt][nt][half * 2 + 1] + hx.y);
                float o0 = zz.x * h0 + (1.0f - zz.x) * ht0;
                float o1 = zz.y * h1 + (1.0f - zz.y) * ht1;
                *(float2*)(out + idx) = make_float2(o0, o1);
                store_h2(g_inp + idx, o0, o1);
            }
        }
}

// ---------------- launch ----------------
extern "C" void kernel_launch(void* const* d_in, const int* in_sizes, int n_in,
                              void* d_out, int out_size) {
    const float* x  = (const float*)d_in[0];
    const float* h  = (const float*)d_in[1];
    const float* Wl = (const float*)d_in[2];
    const float* Wr = (const float*)d_in[3];
    const float* b  = (const float*)d_in[4];
    const int* src  = (const int*)d_in[5];
    const int* dst  = (const int*)d_in[6];
    float* out = (float*)d_out;

    cudaFuncSetAttribute(k_gemm1, cudaFuncAttributeMaxDynamicSharedMemorySize, GSMEM1);
    cudaFuncSetAttribute(k_gemm2, cudaFuncAttributeMaxDynamicSharedMemorySize, GSMEM1);

    const int ROWT = (NN + 127) / 128;
    const int WTOT = LL * 384 * 512 + LL * 128 * 256 + LL * 384;
    const int PREPN = EE + CONVN + LL * CONVN + WTOT;

    k_countscan<<<NCHUNK, 1024>>>(dst);
    k_prep<<<(PREPN + 255) / 256, 256>>>(src, dst, x, h, Wl, Wr, b);

    for (int l = 0; l < LL; l++) {
        const float* hl = h + (size_t)l * NN * DD;
        k_agg2<<<(NN * 32 + 255) / 256, 256>>>(l);
        dim3 g1(6, ROWT);
        k_gemm1<<<g1, 256, GSMEM1>>>(hl, l);   // launch #4 <- ncu target
        k_agg1<<<(NN * 32 + 255) / 256, 256>>>();
        dim3 g2(2, ROWT);
        k_gemm2<<<g2, 256, GSMEM1>>>(hl, out + (size_t)l * NN * DD, l);
    }

    k_zero_end<<<(NN + 255) / 256, 256>>>();
}

// round 15
// speedup vs baseline: 1.7703x; 1.0267x over previous
#include <cuda_runtime.h>
#include <cuda_fp16.h>
#include <math.h>
#include <stdint.h>

// Problem constants (fixed by setup_inputs)
#define NN 50000
#define EE 800000
#define DD 128
#define LL 2
#define NCHUNK ((NN + 1023) / 1024)
#define CONVN (NN * DD / 4)

// ---------------- scratch (static __device__ globals; no allocation) ----------------
__device__ float g_bias[LL * 384];
__device__ float g_invdeg[NN];
__device__ int g_rowptr[NN + 1];
__device__ int g_cursor[NN];
__device__ int g_esrc[EE];

__device__ __align__(16) __half g_Z[NN * DD];
__device__ __align__(16) __half g_HX[NN * DD];
__device__ __align__(16) __half g_inp[NN * DD];
__device__ __align__(16) __half g_h[LL * NN * DD];
__device__ __align__(16) __half g_agga[NN * DD];
__device__ __align__(16) __half g_aggb[NN * DD];
__device__ __align__(16) __half g_rh[NN * DD];
__device__ __align__(16) __half g_W1T[LL * 384 * 512];
__device__ __align__(16) __half g_W2T[LL * 128 * 256];

// ---------------- helpers ----------------
__device__ __forceinline__ uint32_t smem_u32(const void* p) {
    uint32_t a;
    asm("{ .reg .u64 t; cvta.to.shared.u64 t, %1; cvt.u32.u64 %0, t; }" : "=r"(a) : "l"(p));
    return a;
}
__device__ __forceinline__ void ldsm4(uint32_t* f, uint32_t addr) {
    asm volatile("ldmatrix.sync.aligned.m8n8.x4.shared.b16 {%0,%1,%2,%3}, [%4];"
                 : "=r"(f[0]), "=r"(f[1]), "=r"(f[2]), "=r"(f[3]) : "r"(addr));
}
__device__ __forceinline__ void mma16816(float* c, const uint32_t* a, uint32_t b0, uint32_t b1) {
    asm volatile(
        "mma.sync.aligned.m16n8k16.row.col.f32.f16.f16.f32 "
        "{%0,%1,%2,%3}, {%4,%5,%6,%7}, {%8,%9}, {%0,%1,%2,%3};"
        : "+f"(c[0]), "+f"(c[1]), "+f"(c[2]), "+f"(c[3])
        : "r"(a[0]), "r"(a[1]), "r"(a[2]), "r"(a[3]), "r"(b0), "r"(b1));
}
__device__ __forceinline__ void cpa16(uint32_t dst, const void* src, int sz) {
    asm volatile("cp.async.cg.shared.global [%0], [%1], 16, %2;"
                 :: "r"(dst), "l"(src), "r"(sz) : "memory");
}
#define CPA_COMMIT() asm volatile("cp.async.commit_group;" ::: "memory")
#define CPA_WAIT2()  asm volatile("cp.async.wait_group 2;" ::: "memory")

__device__ __forceinline__ void store_h4(__half* d, float4 v) {
    __half2 h0 = __floats2half2_rn(v.x, v.y);
    __half2 h1 = __floats2half2_rn(v.z, v.w);
    uint2 u;
    u.x = *(uint32_t*)&h0;
    u.y = *(uint32_t*)&h1;
    *(uint2*)d = u;
}
__device__ __forceinline__ void store_h2(__half* d, float a, float b) {
    __half2 hh = __floats2half2_rn(a, b);
    *(uint32_t*)d = *(uint32_t*)&hh;
}
// fast MUFU-path transcendentals (rel err ~1e-6, invisible vs fp16 path error)
__device__ __forceinline__ float sigf(float x) { return 1.0f / (1.0f + __expf(-x)); }
__device__ __forceinline__ float tanh_fast(float x) {
    float t = __expf(2.0f * x);
    return 1.0f - 2.0f / (t + 1.0f);
}

// SMEM tile geometry: padded row stride 80B (conflict-free ldmatrix)
#define TROW 80
#define ATB (128 * TROW)           // A subtile: 128 rows x 32 cols  (10240)
#define BTB (64 * TROW)            // B subtile: 64 rows x 32 cols (5120)
#define SUB1 (ATB + BTB)           // 15360: one K32 pipeline stage
#define GSMEM1 (4 * SUB1)          // 61440: 4-stage ring

// precomputed per-thread tile-load state
struct Pre {
    uint32_t sm0, sm1;
    size_t a0, a1;
    int az0, az1;
    size_t b0, b1;
};

__device__ __forceinline__ Pre make_pre(int t, int row0, int col0, int strideB) {
    Pre p;
    int q = t & 3;
    int r0 = t >> 2, r1 = r0 + 64;
    p.sm0 = (uint32_t)(r0 * TROW + q * 16);
    p.sm1 = (uint32_t)(r1 * TROW + q * 16);
    int gr0 = row0 + r0, gr1 = row0 + r1;
    p.az0 = gr0 < NN ? 16 : 0;
    p.az1 = gr1 < NN ? 16 : 0;
    if (gr0 >= NN) gr0 = 0;
    if (gr1 >= NN) gr1 = 0;
    p.a0 = (size_t)gr0 * 128 + q * 8;
    p.a1 = (size_t)gr1 * 128 + q * 8;
    p.b0 = (size_t)(col0 + r0) * strideB + q * 8;
    p.b1 = (size_t)(col0 + r1) * strideB + q * 8;
    return p;
}

// one K32 stage: A 128x32 + B 64x32
__device__ __forceinline__ void load_sub1(uint32_t buf,
                                          const __half* __restrict__ a,
                                          const __half* __restrict__ b,
                                          int colA, int colB, const Pre& p) {
    cpa16(buf + p.sm0,       a + p.a0 + colA, p.az0);
    cpa16(buf + p.sm1,       a + p.a1 + colA, p.az1);
    cpa16(buf + ATB + p.sm0, b + p.b0 + colB, 16);
}

// ---------------- CSR: fused count+scan ----------------
__global__ void __launch_bounds__(1024)
k_countscan(const int* __restrict__ dst) {
    __shared__ int hist[1024];
    __shared__ int ws[32];
    __shared__ int sbase;
    int b = blockIdx.x, t = threadIdx.x;
    int lane = t & 31, wid = t >> 5;
    hist[t] = 0;
    __syncthreads();

    int lo = b << 10;
    int pre = 0;
    const int4* d4 = (const int4*)dst;
    for (int e = t; e < EE / 4; e += 1024) {
        int4 v = __ldg(d4 + e);
        pre += (v.x < lo) + (v.y < lo) + (v.z < lo) + (v.w < lo);
        int dx;
        dx = v.x - lo; if ((unsigned)dx < 1024u) atomicAdd(&hist[dx], 1);
        dx = v.y - lo; if ((unsigned)dx < 1024u) atomicAdd(&hist[dx], 1);
        dx = v.z - lo; if ((unsigned)dx < 1024u) atomicAdd(&hist[dx], 1);
        dx = v.w - lo; if ((unsigned)dx < 1024u) atomicAdd(&hist[dx], 1);
    }
#pragma unroll
    for (int o = 16; o > 0; o >>= 1) pre += __shfl_down_sync(0xffffffffu, pre, o);
    if (lane == 0) ws[wid] = pre;
    __syncthreads();
    if (t < 32) {
        int s = ws[t];
#pragma unroll
        for (int o = 16; o > 0; o >>= 1) s += __shfl_down_sync(0xffffffffu, s, o);
        if (t == 0) sbase = s;
    }
    __syncthreads();
    int base = sbase;
    int v = hist[t];
    __syncthreads();

    int x = v;
#pragma unroll
    for (int o = 1; o < 32; o <<= 1) {
        int y = __shfl_up_sync(0xffffffffu, x, o);
        if (lane >= o) x += y;
    }
    if (lane == 31) ws[wid] = x;
    __syncthreads();
    if (wid == 0) {
        int s = ws[lane];
        int xs = s;
#pragma unroll
        for (int o = 1; o < 32; o <<= 1) {
            int y = __shfl_up_sync(0xffffffffu, xs, o);
            if (lane >= o) xs += y;
        }
        ws[lane] = xs - s;
    }
    __syncthreads();
    int incl = x + ws[wid];
    int i = lo + t;
    if (i < NN) {
        g_rowptr[i] = base + incl - v;
        g_invdeg[i] = 1.0f / fmaxf((float)v, 1.0f);
    }
    if (b == 0 && t == 0) g_rowptr[NN] = EE;
}

// ---------------- fused prep ----------------
__global__ void k_prep(const int* __restrict__ src, const int* __restrict__ dst,
                       const float* __restrict__ x, const float* __restrict__ h,
                       const float* __restrict__ Wl, const float* __restrict__ Wr,
                       const float* __restrict__ b) {
    const int W1TN = LL * 384 * 512;
    const int W2TN = LL * 128 * 256;
    int i = blockIdx.x * blockDim.x + threadIdx.x;
    if (i < EE) {
        int d = dst[i];
        int p = atomicAdd(&g_cursor[d], 1);
        g_esrc[g_rowptr[d] + p] = src[i];
    } else if (i < EE + CONVN) {
        int j = i - EE;
        float4 v = __ldg((const float4*)x + j);
        store_h4(g_inp + (size_t)j * 4, v);
    } else if (i < EE + CONVN + LL * CONVN) {
        int j = i - EE - CONVN;
        float4 v = __ldg((const float4*)h + j);
        store_h4(g_h + (size_t)j * 4, v);
    } else {
        int j = i - EE - CONVN - LL * CONVN;
        if (j < W1TN) {
            int l = j / (384 * 512);
            int rem = j % (384 * 512);
            int c = rem / 512, k = rem % 512;
            int cb = c >> 7, cc = c & 127;
            int s = k >> 7, kk = k & 127;
            float v = 0.0f;
            if (!(cb == 2 && s >= 2)) {
                int g = cb * 2 + (s >> 1);
                const float* W = (s & 1) ? Wr : Wl;
                v = W[(((size_t)l * 6 + g) * 128 + kk) * 128 + cc];
            }
            g_W1T[j] = __float2half_rn(v);
        } else if (j < W1TN + W2TN) {
            int j2 = j - W1TN;
            int l = j2 / (128 * 256);
            int rem = j2 % (128 * 256);
            int c = rem / 256, k = rem % 256;
            int s = k >> 7, kk = k & 127;
            const float* W = s ? Wr : Wl;
            float v = W[(((size_t)l * 6 + 5) * 128 + kk) * 128 + c];
            g_W2T[j2] = __float2half_rn(v);
        } else if (j < W1TN + W2TN + LL * 384) {
            int j2 = j - W1TN - W2TN;
            int l = j2 / 384;
            int c = j2 % 384;
            int cb = c >> 7, cc = c & 127;
            g_bias[j2] = b[(((size_t)l * 6 + cb * 2) * 128) + cc] +
                         b[(((size_t)l * 6 + cb * 2 + 1) * 128) + cc];
        }
    }
}

__global__ void k_zero_end() {
    int i = blockIdx.x * blockDim.x + threadIdx.x;
    if (i < NN) g_cursor[i] = 0;
}

// ---------------- aggregation ----------------
__global__ void k_agg2(int l) {
    int warp = (blockIdx.x * blockDim.x + threadIdx.x) >> 5;
    int lane = threadIdx.x & 31;
    if (warp >= NN) return;
    const __half* __restrict__ A = g_inp;
    const __half* __restrict__ B = g_h + (size_t)l * NN * DD;
    int e = g_rowptr[warp], end = g_rowptr[warp + 1];
    float4 aa = make_float4(0.f, 0.f, 0.f, 0.f);
    float4 ab = make_float4(0.f, 0.f, 0.f, 0.f);
#define ACC4(dst, v) do { \
        float2 _p0 = __half22float2(*(__half2*)&(v).x); \
        float2 _p1 = __half22float2(*(__half2*)&(v).y); \
        dst.x += _p0.x; dst.y += _p0.y; dst.z += _p1.x; dst.w += _p1.y; } while (0)
    for (; e + 3 < end; e += 4) {
        int s0 = g_esrc[e], s1 = g_esrc[e + 1], s2 = g_esrc[e + 2], s3 = g_esrc[e + 3];
        uint2 va0 = __ldg((const uint2*)(A + (size_t)s0 * DD) + lane);
        uint2 va1 = __ldg((const uint2*)(A + (size_t)s1 * DD) + lane);
        uint2 va2 = __ldg((const uint2*)(A + (size_t)s2 * DD) + lane);
        uint2 va3 = __ldg((const uint2*)(A + (size_t)s3 * DD) + lane);
        uint2 vb0 = __ldg((const uint2*)(B + (size_t)s0 * DD) + lane);
        uint2 vb1 = __ldg((const uint2*)(B + (size_t)s1 * DD) + lane);
        uint2 vb2 = __ldg((const uint2*)(B + (size_t)s2 * DD) + lane);
        uint2 vb3 = __ldg((const uint2*)(B + (size_t)s3 * DD) + lane);
        ACC4(aa, va0); ACC4(aa, va1); ACC4(aa, va2); ACC4(aa, va3);
        ACC4(ab, vb0); ACC4(ab, vb1); ACC4(ab, vb2); ACC4(ab, vb3);
    }
    for (; e < end; e++) {
        int s0 = g_esrc[e];
        uint2 va0 = __ldg((const uint2*)(A + (size_t)s0 * DD) + lane);
        uint2 vb0 = __ldg((const uint2*)(B + (size_t)s0 * DD) + lane);
        ACC4(aa, va0); ACC4(ab, vb0);
    }
    float sc = g_invdeg[warp];
    aa.x *= sc; aa.y *= sc; aa.z *= sc; aa.w *= sc;
    ab.x *= sc; ab.y *= sc; ab.z *= sc; ab.w *= sc;
    size_t o = (size_t)warp * DD + lane * 4;
    store_h4(g_agga + o, aa);
    store_h4(g_aggb + o, ab);
}

__global__ void k_agg1() {
    int warp = (blockIdx.x * blockDim.x + threadIdx.x) >> 5;
    int lane = threadIdx.x & 31;
    if (warp >= NN) return;
    int e = g_rowptr[warp], end = g_rowptr[warp + 1];
    float4 aa = make_float4(0.f, 0.f, 0.f, 0.f);
    for (; e + 3 < end; e += 4) {
        int s0 = g_esrc[e], s1 = g_esrc[e + 1], s2 = g_esrc[e + 2], s3 = g_esrc[e + 3];
        uint2 v0 = __ldg((const uint2*)(g_rh + (size_t)s0 * DD) + lane);
        uint2 v1 = __ldg((const uint2*)(g_rh + (size_t)s1 * DD) + lane);
        uint2 v2 = __ldg((const uint2*)(g_rh + (size_t)s2 * DD) + lane);
        uint2 v3 = __ldg((const uint2*)(g_rh + (size_t)s3 * DD) + lane);
        ACC4(aa, v0); ACC4(aa, v1); ACC4(aa, v2); ACC4(aa, v3);
    }
    for (; e < end; e++) {
        int s0 = g_esrc[e];
        uint2 v0 = __ldg((const uint2*)(g_rh + (size_t)s0 * DD) + lane);
        ACC4(aa, v0);
    }
    float sc = g_invdeg[warp];
    aa.x *= sc; aa.y *= sc; aa.z *= sc; aa.w *= sc;
    store_h4(g_agga + (size_t)warp * DD + lane * 4, aa);
}
#undef ACC4

// ---------------- HMMA core: 32x32 warp tile, one K32 stage ----------------
__device__ __forceinline__ void gemm_sub1(uint32_t sA, uint32_t lsm_a, uint32_t lsm_b,
                                          float acc[2][4][4]) {
    uint32_t sB = sA + ATB;
#pragma unroll
    for (int kb = 0; kb < 2; kb++) {
        uint32_t ko = kb * 32;
        uint32_t Af[2][4], Bf[2][4];
        ldsm4(Af[0], sA + lsm_a + ko);
        ldsm4(Af[1], sA + lsm_a + ko + 16 * TROW);
        ldsm4(Bf[0], sB + lsm_b + ko);
        ldsm4(Bf[1], sB + lsm_b + ko + 16 * TROW);
#pragma unroll
        for (int mt = 0; mt < 2; mt++)
#pragma unroll
            for (int nt = 0; nt < 4; nt++) {
                int ng = nt >> 1, o = nt & 1;
                mma16816(acc[mt][nt], Af[mt], Bf[ng][o], Bf[ng][o + 2]);
            }
    }
}

// ---------------- GEMM1: CTA 128x64, warp 32x32, 3 CTAs/SM, 4-stage K32 pipeline ----------------
__global__ void __launch_bounds__(256, 3)
k_gemm1(const float* __restrict__ hl, int l) {
    extern __shared__ __align__(16) char smdyn[];
    uint32_t sb = smem_u32(smdyn);
    int t = threadIdx.x;
    int row0 = blockIdx.y * 128;
    int cb64 = blockIdx.x;
    int col0 = cb64 * 64;
    int cb = cb64 >> 1;
    const int S = (cb == 2) ? 8 : 16;   // K32 steps

    const __half* __restrict__ W = g_W1T + (size_t)l * 384 * 512;
    const __half* segs[4] = { g_agga, g_inp, g_aggb, g_h + (size_t)l * NN * DD };

    const Pre p = make_pre(t, row0, col0, 512);
    int lane = t & 31, wid = t >> 5;
    int wm = wid & 3, wn = wid >> 2;
    uint32_t rsel = (uint32_t)(lane & 15) * TROW + (uint32_t)(lane >> 4) * 16;
    uint32_t lsm_a = (uint32_t)(wm * 32) * TROW + rsel;
    uint32_t lsm_b = (uint32_t)(wn * 32) * TROW + rsel;

    float acc[2][4][4];
#pragma unroll
    for (int i = 0; i < 2; i++)
#pragma unroll
        for (int j = 0; j < 4; j++)
#pragma unroll
            for (int q = 0; q < 4; q++) acc[i][j][q] = 0.0f;

    // prologue: stages 0..2
#pragma unroll
    for (int s = 0; s < 3; s++) {
        load_sub1(sb + s * SUB1, segs[s >> 2], W, (s & 3) * 32, s * 32, p);
        CPA_COMMIT();
    }
    for (int s = 0; s < S; s++) {
        CPA_WAIT2();          // stage s data resident (all but 2 newest groups done)
        __syncthreads();      // all warps done computing stage s-1 -> buf[(s+3)&3] reusable
        int sn = s + 3;
        if (sn < S)
            load_sub1(sb + (sn & 3) * SUB1, segs[sn >> 2], W, (sn & 3 & 3) * 32, sn * 32, p);
        CPA_COMMIT();         // always commit (possibly empty) to keep group count invariant
        gemm_sub1(sb + (s & 3) * SUB1, lsm_a, lsm_b, acc);
    }

    // epilogue
    const float* bias = g_bias + l * 384;
#pragma unroll
    for (int mt = 0; mt < 2; mt++)
#pragma unroll
        for (int nt = 0; nt < 4; nt++) {
            int row = row0 + wm * 32 + mt * 16 + (lane >> 2);
            int col = col0 + wn * 32 + nt * 8 + (lane & 3) * 2;
            float b0 = __ldg(bias + col), b1 = __ldg(bias + col + 1);
            int ccol = col & 127;
#pragma unroll
            for (int half = 0; half < 2; half++) {
                int r = row + half * 8;
                if (r >= NN) continue;
                float v0 = acc[mt][nt][half * 2 + 0] + b0;
                float v1 = acc[mt][nt][half * 2 + 1] + b1;
                size_t idx = (size_t)r * 128 + ccol;
                if (cb == 0) {
                    store_h2(g_Z + idx, sigf(v0), sigf(v1));
                } else if (cb == 1) {
                    float h0 = hl[idx], h1 = hl[idx + 1];
                    store_h2(g_rh + idx, sigf(v0) * h0, sigf(v1) * h1);
                } else {
                    store_h2(g_HX + idx, v0, v1);
                }
            }
        }
}

// ---------------- GEMM2: CTA 128x64, warp 32x32, 3 CTAs/SM, 4-stage K32 pipeline ----------------
__global__ void __launch_bounds__(256, 3)
k_gemm2(const float* __restrict__ hl, float* __restrict__ out, int l) {
    extern __shared__ __align__(16) char smdyn[];
    uint32_t sb = smem_u32(smdyn);
    int t = threadIdx.x;
    int row0 = blockIdx.y * 128;
    int col0 = blockIdx.x * 64;
    const int S = 8;

    const __half* __restrict__ W = g_W2T + (size_t)l * 128 * 256;
    const __half* segs[2] = { g_agga, g_rh };

    const Pre p = make_pre(t, row0, col0, 256);
    int lane = t & 31, wid = t >> 5;
    int wm = wid & 3, wn = wid >> 2;
    uint32_t rsel = (uint32_t)(lane & 15) * TROW + (uint32_t)(lane >> 4) * 16;
    uint32_t lsm_a = (uint32_t)(wm * 32) * TROW + rsel;
    uint32_t lsm_b = (uint32_t)(wn * 32) * TROW + rsel;

    float acc[2][4][4];
#pragma unroll
    for (int i = 0; i < 2; i++)
#pragma unroll
        for (int j = 0; j < 4; j++)
#pragma unroll
            for (int q = 0; q < 4; q++) acc[i][j][q] = 0.0f;

#pragma unroll
    for (int s = 0; s < 3; s++) {
        load_sub1(sb + s * SUB1, segs[s >> 2], W, (s & 3) * 32, s * 32, p);
        CPA_COMMIT();
    }
    for (int s = 0; s < S; s++) {
        CPA_WAIT2();
        __syncthreads();
        int sn = s + 3;
        if (sn < S)
            load_sub1(sb + (sn & 3) * SUB1, segs[sn >> 2], W, (sn & 3) * 32, sn * 32, p);
        CPA_COMMIT();
        gemm_sub1(sb + (s & 3) * SUB1, lsm_a, lsm_b, acc);
    }

#pragma unroll
    for (int mt = 0; mt < 2; mt++)
#pragma unroll
        for (int nt = 0; nt < 4; nt++) {
            int row = row0 + wm * 32 + mt * 16 + (lane >> 2);
            int col = col0 + wn * 32 + nt * 8 + (lane & 3) * 2;
#pragma unroll
            for (int half = 0; half < 2; half++) {
                int r = row + half * 8;
                if (r >= NN) continue;
                size_t idx = (size_t)r * 128 + col;
                float2 hx = __half22float2(*(const __half2*)(g_HX + idx));
                float2 zz = __half22float2(*(const __half2*)(g_Z + idx));
                float h0 = hl[idx], h1 = hl[idx + 1];
                float ht0 = tanh_fast(acc[mt][nt][half * 2 + 0] + hx.x);
                float ht1 = tanh_fast(acc[mt][nt][half * 2 + 1] + hx.y);
                float o0 = zz.x * h0 + (1.0f - zz.x) * ht0;
                float o1 = zz.y * h1 + (1.0f - zz.y) * ht1;
                *(float2*)(out + idx) = make_float2(o0, o1);
                store_h2(g_inp + idx, o0, o1);
            }
        }
}

// ---------------- launch ----------------
extern "C" void kernel_launch(void* const* d_in, const int* in_sizes, int n_in,
                              void* d_out, int out_size) {
    const float* x  = (const float*)d_in[0];
    const float* h  = (const float*)d_in[1];
    const float* Wl = (const float*)d_in[2];
    const float* Wr = (const float*)d_in[3];
    const float* b  = (const float*)d_in[4];
    const int* src  = (const int*)d_in[5];
    const int* dst  = (const int*)d_in[6];
    float* out = (float*)d_out;

    cudaFuncSetAttribute(k_gemm1, cudaFuncAttributeMaxDynamicSharedMemorySize, GSMEM1);
    cudaFuncSetAttribute(k_gemm2, cudaFuncAttributeMaxDynamicSharedMemorySize, GSMEM1);

    const int ROWT = (NN + 127) / 128;
    const int WTOT = LL * 384 * 512 + LL * 128 * 256 + LL * 384;
    const int PREPN = EE + CONVN + LL * CONVN + WTOT;

    k_countscan<<<NCHUNK, 1024>>>(dst);
    k_prep<<<(PREPN + 255) / 256, 256>>>(src, dst, x, h, Wl, Wr, b);

    for (int l = 0; l < LL; l++) {
        const float* hl = h + (size_t)l * NN * DD;
        k_agg2<<<(NN * 32 + 255) / 256, 256>>>(l);
        dim3 g1(6, ROWT);
        k_gemm1<<<g1, 256, GSMEM1>>>(hl, l);   // launch #4 <- ncu target
        k_agg1<<<(NN * 32 + 255) / 256, 256>>>();
        dim3 g2(2, ROWT);
        k_gemm2<<<g2, 256, GSMEM1>>>(hl, out + (size_t)l * NN * DD, l);
    }

    k_zero_end<<<(NN + 255) / 256, 256>>>();
}